// round 1
// baseline (speedup 1.0000x reference)
#include <cuda_runtime.h>
#include <math.h>

#define DIMC   1024
#define NHEADS 16
#define HDIM   64
#define BB     2
#define LL     1024
#define SS     2048
#define QSCALE 0.125f  /* 64^-0.5 */

// ---------------- device scratch (no allocations allowed) ----------------
__device__ float g_Q[BB * LL * DIMC];   // 8 MB
__device__ float g_K[BB * SS * DIMC];   // 16 MB
__device__ float g_V[BB * SS * DIMC];   // 16 MB
__device__ float g_X[BB * LL * DIMC];   // 8 MB

// ---------------- tiled fp32 GEMM: C[M,1024] = A[M,1024] @ W[1024,1024] (+bias) ----
// 64x64 block tile, BK=16, 256 threads, 4x4 per thread.
__global__ void gemm_k(const float* __restrict__ A,
                       const float* __restrict__ W,
                       const float* __restrict__ bias,
                       float* __restrict__ C)
{
    __shared__ float As[16][64];   // As[k][m]
    __shared__ float Ws[16][64];   // Ws[k][n]

    const int bm  = blockIdx.y * 64;
    const int bn  = blockIdx.x * 64;
    const int tid = threadIdx.x;
    const int tm  = (tid >> 4) * 4;     // 0..60
    const int tn  = (tid & 15) * 4;     // 0..60

    float acc[4][4];
#pragma unroll
    for (int i = 0; i < 4; i++)
#pragma unroll
        for (int j = 0; j < 4; j++) acc[i][j] = 0.f;

    // A-load mapping: thread loads 4 contiguous k at (m = tid/4, k = (tid%4)*4)
    const int am = tid >> 2;
    const int ak = (tid & 3) * 4;
    // W-load mapping: thread loads 4 contiguous n at (k = tid/16, n = (tid%16)*4)
    const int wk = tid >> 4;
    const int wn = (tid & 15) * 4;

    for (int k0 = 0; k0 < DIMC; k0 += 16) {
        float4 av = *reinterpret_cast<const float4*>(
            &A[(size_t)(bm + am) * DIMC + k0 + ak]);
        As[ak + 0][am] = av.x;
        As[ak + 1][am] = av.y;
        As[ak + 2][am] = av.z;
        As[ak + 3][am] = av.w;

        float4 wv = *reinterpret_cast<const float4*>(
            &W[(size_t)(k0 + wk) * DIMC + bn + wn]);
        *reinterpret_cast<float4*>(&Ws[wk][wn]) = wv;

        __syncthreads();

#pragma unroll
        for (int k = 0; k < 16; k++) {
            float a0 = As[k][tm + 0];
            float a1 = As[k][tm + 1];
            float a2 = As[k][tm + 2];
            float a3 = As[k][tm + 3];
            float4 w4 = *reinterpret_cast<const float4*>(&Ws[k][tn]);
            acc[0][0] += a0 * w4.x; acc[0][1] += a0 * w4.y; acc[0][2] += a0 * w4.z; acc[0][3] += a0 * w4.w;
            acc[1][0] += a1 * w4.x; acc[1][1] += a1 * w4.y; acc[1][2] += a1 * w4.z; acc[1][3] += a1 * w4.w;
            acc[2][0] += a2 * w4.x; acc[2][1] += a2 * w4.y; acc[2][2] += a2 * w4.z; acc[2][3] += a2 * w4.w;
            acc[3][0] += a3 * w4.x; acc[3][1] += a3 * w4.y; acc[3][2] += a3 * w4.z; acc[3][3] += a3 * w4.w;
        }
        __syncthreads();
    }

    float bv[4] = {0.f, 0.f, 0.f, 0.f};
    if (bias) {
#pragma unroll
        for (int j = 0; j < 4; j++) bv[j] = bias[bn + tn + j];
    }
#pragma unroll
    for (int i = 0; i < 4; i++) {
        float4 o;
        o.x = acc[i][0] + bv[0];
        o.y = acc[i][1] + bv[1];
        o.z = acc[i][2] + bv[2];
        o.w = acc[i][3] + bv[3];
        *reinterpret_cast<float4*>(&C[(size_t)(bm + tm + i) * DIMC + bn + tn]) = o;
    }
}

// ---------------- flash-style attention, one warp per query row --------------
// grid: (L/8, B*H), block 256 (8 warps). K/V staged in smem 64-key tiles.
__global__ void attn_k(const float* __restrict__ Q,
                       const float* __restrict__ K,
                       const float* __restrict__ V,
                       float* __restrict__ X)
{
    __shared__ float Ks[64 * 65];
    __shared__ float Vs[64 * 65];
    __shared__ float qs[8][64];
    __shared__ float ps[8][64];

    const int bh   = blockIdx.y;
    const int b    = bh >> 4;
    const int h    = bh & 15;
    const int warp = threadIdx.x >> 5;
    const int lane = threadIdx.x & 31;
    const int row  = blockIdx.x * 8 + warp;

    const float* qptr = Q + ((size_t)(b * LL + row) * DIMC + h * HDIM);
    qs[warp][lane]      = qptr[lane]      * QSCALE;
    qs[warp][lane + 32] = qptr[lane + 32] * QSCALE;

    float m = -INFINITY, lsum = 0.f, o0 = 0.f, o1 = 0.f;

    const float* Kbase = K + (size_t)b * SS * DIMC + h * HDIM;
    const float* Vbase = V + (size_t)b * SS * DIMC + h * HDIM;

    for (int s0 = 0; s0 < SS; s0 += 64) {
        __syncthreads();   // guard Ks/Vs from previous-iter consumers
        // cooperative tile load: 64 keys x 64 dims, float4 per thread-iter
        for (int i = threadIdx.x; i < 1024; i += 256) {
            int r = i >> 4;
            int d = (i & 15) * 4;
            float4 kv = *reinterpret_cast<const float4*>(
                &Kbase[(size_t)(s0 + r) * DIMC + d]);
            float4 vv = *reinterpret_cast<const float4*>(
                &Vbase[(size_t)(s0 + r) * DIMC + d]);
            float* kp = &Ks[r * 65 + d];
            kp[0] = kv.x; kp[1] = kv.y; kp[2] = kv.z; kp[3] = kv.w;
            float* vp = &Vs[r * 65 + d];
            vp[0] = vv.x; vp[1] = vv.y; vp[2] = vv.z; vp[3] = vv.w;
        }
        __syncthreads();

        // scores for keys j = lane and j = lane+32 (conflict-free with pad 65)
        float sc0 = 0.f, sc1 = 0.f;
#pragma unroll
        for (int d = 0; d < 64; d++) {
            float q = qs[warp][d];
            sc0 += q * Ks[lane * 65 + d];
            sc1 += q * Ks[(lane + 32) * 65 + d];
        }

        float mt = fmaxf(sc0, sc1);
#pragma unroll
        for (int off = 16; off; off >>= 1)
            mt = fmaxf(mt, __shfl_xor_sync(0xffffffffu, mt, off));
        float mnew = fmaxf(m, mt);
        float corr = __expf(m - mnew);
        float p0 = __expf(sc0 - mnew);
        float p1 = __expf(sc1 - mnew);
        float psum = p0 + p1;
#pragma unroll
        for (int off = 16; off; off >>= 1)
            psum += __shfl_xor_sync(0xffffffffu, psum, off);
        lsum = lsum * corr + psum;
        o0 *= corr;
        o1 *= corr;
        m = mnew;

        ps[warp][lane]      = p0;
        ps[warp][lane + 32] = p1;
        __syncwarp();

        // accumulate O[d] for d = lane, lane+32
#pragma unroll
        for (int j = 0; j < 64; j++) {
            float p = ps[warp][j];
            o0 += p * Vs[j * 65 + lane];
            o1 += p * Vs[j * 65 + lane + 32];
        }
    }

    float inv = 1.f / lsum;
    float* xptr = X + ((size_t)(b * LL + row) * DIMC + h * HDIM);
    xptr[lane]      = o0 * inv;
    xptr[lane + 32] = o1 * inv;
}

// ------------------------------- launch ------------------------------------
extern "C" void kernel_launch(void* const* d_in, const int* in_sizes, int n_in,
                              void* d_out, int out_size)
{
    const float* query = (const float*)d_in[0];
    const float* key   = (const float*)d_in[1];
    const float* value = (const float*)d_in[2];
    const float* Wq    = (const float*)d_in[3];
    const float* Wk    = (const float*)d_in[4];
    const float* Wv    = (const float*)d_in[5];
    const float* Wo    = (const float*)d_in[6];
    const float* bo    = (const float*)d_in[7];
    float* out = (float*)d_out;

    float *Qp, *Kp, *Vp, *Xp;
    cudaGetSymbolAddress((void**)&Qp, g_Q);
    cudaGetSymbolAddress((void**)&Kp, g_K);
    cudaGetSymbolAddress((void**)&Vp, g_V);
    cudaGetSymbolAddress((void**)&Xp, g_X);

    dim3 blk(256);
    // projections
    gemm_k<<<dim3(16, (BB * LL) / 64), blk>>>(query, Wq, nullptr, Qp);
    gemm_k<<<dim3(16, (BB * SS) / 64), blk>>>(key,   Wk, nullptr, Kp);
    gemm_k<<<dim3(16, (BB * SS) / 64), blk>>>(value, Wv, nullptr, Vp);
    // attention
    attn_k<<<dim3(LL / 8, BB * NHEADS), blk>>>(Qp, Kp, Vp, Xp);
    // output projection (+bias) straight into d_out
    gemm_k<<<dim3(16, (BB * LL) / 64), blk>>>(Xp, Wo, bo, out);
}

// round 3
// speedup vs baseline: 2.5395x; 2.5395x over previous
#include <cuda_runtime.h>
#include <cuda_bf16.h>
#include <cstdint>
#include <math.h>

#define DIMC   1024
#define NHEADS 16
#define HDIM   64
#define BB     2
#define LL     1024
#define SS     2048
#define QSCALE 0.125f

// ------------------------- device scratch ----------------------------------
__device__ float g_Q[BB * LL * DIMC];
__device__ float g_K[BB * SS * DIMC];
__device__ float g_V[BB * SS * DIMC];
__device__ float g_X[BB * LL * DIMC];

__device__ __nv_bfloat16 g_qh[BB * LL * DIMC], g_ql[BB * LL * DIMC];
__device__ __nv_bfloat16 g_kh[BB * SS * DIMC], g_kl[BB * SS * DIMC];
__device__ __nv_bfloat16 g_vh[BB * SS * DIMC], g_vl[BB * SS * DIMC];
__device__ __nv_bfloat16 g_xh[BB * LL * DIMC], g_xl[BB * LL * DIMC];
__device__ __nv_bfloat16 g_wqh[DIMC * DIMC], g_wql[DIMC * DIMC];
__device__ __nv_bfloat16 g_wkh[DIMC * DIMC], g_wkl[DIMC * DIMC];
__device__ __nv_bfloat16 g_wvh[DIMC * DIMC], g_wvl[DIMC * DIMC];
__device__ __nv_bfloat16 g_woh[DIMC * DIMC], g_wol[DIMC * DIMC];

// ------------------------- split kernels ------------------------------------
__global__ void split_k(const float* __restrict__ X,
                        __nv_bfloat16* __restrict__ H,
                        __nv_bfloat16* __restrict__ L, int n4)
{
    int i = blockIdx.x * 256 + threadIdx.x;
    if (i >= n4) return;
    float4 x = reinterpret_cast<const float4*>(X)[i];
    __nv_bfloat16 h0 = __float2bfloat16(x.x);
    __nv_bfloat16 h1 = __float2bfloat16(x.y);
    __nv_bfloat16 h2 = __float2bfloat16(x.z);
    __nv_bfloat16 h3 = __float2bfloat16(x.w);
    __nv_bfloat16 l0 = __float2bfloat16(x.x - __bfloat162float(h0));
    __nv_bfloat16 l1 = __float2bfloat16(x.y - __bfloat162float(h1));
    __nv_bfloat16 l2 = __float2bfloat16(x.z - __bfloat162float(h2));
    __nv_bfloat16 l3 = __float2bfloat16(x.w - __bfloat162float(h3));
    reinterpret_cast<__nv_bfloat162*>(H)[2 * i + 0] = __nv_bfloat162(h0, h1);
    reinterpret_cast<__nv_bfloat162*>(H)[2 * i + 1] = __nv_bfloat162(h2, h3);
    reinterpret_cast<__nv_bfloat162*>(L)[2 * i + 0] = __nv_bfloat162(l0, l1);
    reinterpret_cast<__nv_bfloat162*>(L)[2 * i + 1] = __nv_bfloat162(l2, l3);
}

// transpose + split: Th[n][k] = hi(W[k][n]), Tl = residual
__global__ void tsplit_k(const float* __restrict__ W,
                         __nv_bfloat16* __restrict__ Th,
                         __nv_bfloat16* __restrict__ Tl)
{
    __shared__ float t[32][33];
    const int bx = blockIdx.x * 32;  // n
    const int by = blockIdx.y * 32;  // k
    for (int i = threadIdx.y; i < 32; i += 8)
        t[i][threadIdx.x] = W[(size_t)(by + i) * DIMC + bx + threadIdx.x];
    __syncthreads();
    for (int i = threadIdx.y; i < 32; i += 8) {
        int n = bx + i, k = by + threadIdx.x;
        float x = t[threadIdx.x][i];
        __nv_bfloat16 h = __float2bfloat16(x);
        Th[(size_t)n * DIMC + k] = h;
        Tl[(size_t)n * DIMC + k] = __float2bfloat16(x - __bfloat162float(h));
    }
}

// ------------------------- bf16 HMMA helpers ---------------------------------
__device__ __forceinline__ void mma16816(float* d, const uint32_t* a, const uint32_t* b)
{
    asm volatile(
        "mma.sync.aligned.m16n8k16.row.col.f32.bf16.bf16.f32 "
        "{%0,%1,%2,%3}, {%4,%5,%6,%7}, {%8,%9}, {%0,%1,%2,%3};"
        : "+f"(d[0]), "+f"(d[1]), "+f"(d[2]), "+f"(d[3])
        : "r"(a[0]), "r"(a[1]), "r"(a[2]), "r"(a[3]), "r"(b[0]), "r"(b[1]));
}

// ------------------------- HMMA GEMM -----------------------------------------
// C[M,1024] = (Ah+Al)[M,1024] @ (Bth+Btl)^T (+bias)
// Bt stored [n][k]. CTA tile 128x128, BK=64, 8 warps of 64x32.
// smem: per stage 4 matrices of 128x64 bf16, padded row stride 72.
#define SROW 72
#define SMAT (128 * SROW)            // 9216 bf16 elems per matrix
#define SSTAGE (4 * SMAT)            // 36864 elems per stage
#define GEMM_SMEM (2 * SSTAGE * 2)   // bytes = 147456

__global__ void __launch_bounds__(256, 1)
gemm_mma(const __nv_bfloat16* __restrict__ Ah, const __nv_bfloat16* __restrict__ Al,
         const __nv_bfloat16* __restrict__ Bh, const __nv_bfloat16* __restrict__ Bl,
         const float* __restrict__ bias, float* __restrict__ C)
{
    extern __shared__ __align__(16) __nv_bfloat16 sm[];

    const int tid  = threadIdx.x;
    const int lane = tid & 31;
    const int w    = tid >> 5;
    const int wm   = w >> 2;          // 0..1
    const int wn   = w & 3;           // 0..3
    const int bm   = blockIdx.y * 128;
    const int bn   = blockIdx.x * 128;

    float acc[4][4][4];
#pragma unroll
    for (int i = 0; i < 4; i++)
#pragma unroll
        for (int j = 0; j < 4; j++)
#pragma unroll
            for (int c = 0; c < 4; c++) acc[i][j][c] = 0.f;

    // --- tile loader: one chunk (kc) into stage s ---
    auto load_chunk = [&](int s, int kc) {
        __nv_bfloat16* dst = sm + s * SSTAGE;
        const __nv_bfloat16* srcA[2] = {Ah, Al};
        const __nv_bfloat16* srcB[2] = {Bh, Bl};
#pragma unroll
        for (int m = 0; m < 2; m++) {
#pragma unroll
            for (int it = 0; it < 4; it++) {
                int idx = tid + it * 256;          // 0..1023
                int r = idx >> 3, seg = idx & 7;   // row, 16B segment
                *reinterpret_cast<int4*>(dst + m * SMAT + r * SROW + seg * 8) =
                    *reinterpret_cast<const int4*>(
                        srcA[m] + (size_t)(bm + r) * DIMC + kc + seg * 8);
            }
        }
#pragma unroll
        for (int m = 0; m < 2; m++) {
#pragma unroll
            for (int it = 0; it < 4; it++) {
                int idx = tid + it * 256;
                int r = idx >> 3, seg = idx & 7;
                *reinterpret_cast<int4*>(dst + (2 + m) * SMAT + r * SROW + seg * 8) =
                    *reinterpret_cast<const int4*>(
                        srcB[m] + (size_t)(bn + r) * DIMC + kc + seg * 8);
            }
        }
    };

    load_chunk(0, 0);
    __syncthreads();

    const int ar = lane >> 2;            // fragment row within 8
    const int ac = (lane & 3) * 2;       // fragment col pair

    for (int ch = 0; ch < 16; ch++) {
        const int cur = ch & 1;
        if (ch < 15) load_chunk(cur ^ 1, (ch + 1) * 64);

        const __nv_bfloat16* Ahs = sm + cur * SSTAGE;
        const __nv_bfloat16* Als = Ahs + SMAT;
        const __nv_bfloat16* Bhs = Ahs + 2 * SMAT;
        const __nv_bfloat16* Bls = Ahs + 3 * SMAT;

#pragma unroll
        for (int kk = 0; kk < 4; kk++) {
            const int k0 = kk * 16;
            uint32_t ah[4][4], al[4][4], bh[4][2], bl[4][2];
#pragma unroll
            for (int i = 0; i < 4; i++) {
                const __nv_bfloat16* pa = Ahs + (wm * 64 + i * 16 + ar) * SROW + k0 + ac;
                ah[i][0] = *reinterpret_cast<const uint32_t*>(pa);
                ah[i][1] = *reinterpret_cast<const uint32_t*>(pa + 8 * SROW);
                ah[i][2] = *reinterpret_cast<const uint32_t*>(pa + 8);
                ah[i][3] = *reinterpret_cast<const uint32_t*>(pa + 8 * SROW + 8);
                const __nv_bfloat16* pl = Als + (wm * 64 + i * 16 + ar) * SROW + k0 + ac;
                al[i][0] = *reinterpret_cast<const uint32_t*>(pl);
                al[i][1] = *reinterpret_cast<const uint32_t*>(pl + 8 * SROW);
                al[i][2] = *reinterpret_cast<const uint32_t*>(pl + 8);
                al[i][3] = *reinterpret_cast<const uint32_t*>(pl + 8 * SROW + 8);
            }
#pragma unroll
            for (int j = 0; j < 4; j++) {
                const __nv_bfloat16* pb = Bhs + (wn * 32 + j * 8 + ar) * SROW + k0 + ac;
                bh[j][0] = *reinterpret_cast<const uint32_t*>(pb);
                bh[j][1] = *reinterpret_cast<const uint32_t*>(pb + 8);
                const __nv_bfloat16* pc = Bls + (wn * 32 + j * 8 + ar) * SROW + k0 + ac;
                bl[j][0] = *reinterpret_cast<const uint32_t*>(pc);
                bl[j][1] = *reinterpret_cast<const uint32_t*>(pc + 8);
            }
#pragma unroll
            for (int i = 0; i < 4; i++)
#pragma unroll
                for (int j = 0; j < 4; j++) {
                    mma16816(acc[i][j], ah[i], bh[j]);
                    mma16816(acc[i][j], ah[i], bl[j]);
                    mma16816(acc[i][j], al[i], bh[j]);
                }
        }
        __syncthreads();
    }

    // epilogue: registers -> global (float2 stores)
#pragma unroll
    for (int j = 0; j < 4; j++) {
        const int col = bn + wn * 32 + j * 8 + (lane & 3) * 2;
        float b0 = 0.f, b1 = 0.f;
        if (bias) { b0 = bias[col]; b1 = bias[col + 1]; }
#pragma unroll
        for (int i = 0; i < 4; i++) {
            const int row = bm + wm * 64 + i * 16 + (lane >> 2);
            float2 v;
            v.x = acc[i][j][0] + b0;
            v.y = acc[i][j][1] + b1;
            *reinterpret_cast<float2*>(&C[(size_t)row * DIMC + col]) = v;
            v.x = acc[i][j][2] + b0;
            v.y = acc[i][j][3] + b1;
            *reinterpret_cast<float2*>(&C[(size_t)(row + 8) * DIMC + col]) = v;
        }
    }
}

// ------------------------- attention: 8 rows/warp ----------------------------
// dynamic smem: Ks[64*68] Vs[64*68] qs[64*64] ps[64*64] floats = 67584 B
#define ATTN_SMEM ((64 * 68 * 2 + 64 * 64 * 2) * 4)

__global__ void __launch_bounds__(256, 2)
attn_k(const float* __restrict__ Q, const float* __restrict__ K,
       const float* __restrict__ V, float* __restrict__ X)
{
    extern __shared__ __align__(16) float asm_[];
    float* Ks = asm_;                 // 64*68
    float* Vs = Ks + 64 * 68;
    float* qs = Vs + 64 * 68;         // 64*64
    float* ps = qs + 64 * 64;         // 8 warps * 8 * 64

    const int bh = blockIdx.y, b = bh >> 4, h = bh & 15;
    const int warp = threadIdx.x >> 5, lane = threadIdx.x & 31;
    const int r0 = blockIdx.x * 64;

#pragma unroll
    for (int it = 0; it < 4; it++) {
        int c = threadIdx.x + it * 256;
        int r = c >> 4, d4 = (c & 15) * 4;
        float4 qv = *reinterpret_cast<const float4*>(
            &Q[(size_t)(b * LL + r0 + r) * DIMC + h * HDIM + d4]);
        qv.x *= QSCALE; qv.y *= QSCALE; qv.z *= QSCALE; qv.w *= QSCALE;
        *reinterpret_cast<float4*>(&qs[r * 64 + d4]) = qv;
    }

    float m[8], l[8], o0[8], o1[8];
#pragma unroll
    for (int r = 0; r < 8; r++) { m[r] = -INFINITY; l[r] = 0.f; o0[r] = 0.f; o1[r] = 0.f; }

    const float* Kb = K + (size_t)b * SS * DIMC + h * HDIM;
    const float* Vb = V + (size_t)b * SS * DIMC + h * HDIM;
    const int wq = warp * 8;
    float* psw = &ps[warp * 8 * 64];

    for (int s0 = 0; s0 < SS; s0 += 64) {
        __syncthreads();
#pragma unroll
        for (int it = 0; it < 4; it++) {
            int c = threadIdx.x + it * 256;
            int r = c >> 4, d4 = (c & 15) * 4;
            *reinterpret_cast<float4*>(&Ks[r * 68 + d4]) =
                *reinterpret_cast<const float4*>(&Kb[(size_t)(s0 + r) * DIMC + d4]);
            *reinterpret_cast<float4*>(&Vs[r * 68 + d4]) =
                *reinterpret_cast<const float4*>(&Vb[(size_t)(s0 + r) * DIMC + d4]);
        }
        __syncthreads();

        float sa[8], sb[8];
#pragma unroll
        for (int r = 0; r < 8; r++) { sa[r] = 0.f; sb[r] = 0.f; }
#pragma unroll
        for (int d4 = 0; d4 < 64; d4 += 4) {
            float4 k0 = *reinterpret_cast<const float4*>(&Ks[lane * 68 + d4]);
            float4 k1 = *reinterpret_cast<const float4*>(&Ks[(lane + 32) * 68 + d4]);
#pragma unroll
            for (int r = 0; r < 8; r++) {
                float4 q = *reinterpret_cast<const float4*>(&qs[(wq + r) * 64 + d4]);
                sa[r] += q.x * k0.x + q.y * k0.y + q.z * k0.z + q.w * k0.w;
                sb[r] += q.x * k1.x + q.y * k1.y + q.z * k1.z + q.w * k1.w;
            }
        }

#pragma unroll
        for (int r = 0; r < 8; r++) {
            float mt = fmaxf(sa[r], sb[r]);
#pragma unroll
            for (int off = 16; off; off >>= 1)
                mt = fmaxf(mt, __shfl_xor_sync(0xffffffffu, mt, off));
            float mn = fmaxf(m[r], mt);
            float corr = __expf(m[r] - mn);
            float p0 = __expf(sa[r] - mn);
            float p1 = __expf(sb[r] - mn);
            float pp = p0 + p1;
#pragma unroll
            for (int off = 16; off; off >>= 1)
                pp += __shfl_xor_sync(0xffffffffu, pp, off);
            l[r] = l[r] * corr + pp;
            o0[r] *= corr; o1[r] *= corr;
            m[r] = mn;
            psw[r * 64 + lane] = p0;
            psw[r * 64 + lane + 32] = p1;
        }
        __syncwarp();

#pragma unroll
        for (int j4 = 0; j4 < 64; j4 += 4) {
            float4 p[8];
#pragma unroll
            for (int r = 0; r < 8; r++)
                p[r] = *reinterpret_cast<const float4*>(&psw[r * 64 + j4]);
#pragma unroll
            for (int jj = 0; jj < 4; jj++) {
                float v0 = Vs[(j4 + jj) * 68 + lane];
                float v1 = Vs[(j4 + jj) * 68 + lane + 32];
#pragma unroll
                for (int r = 0; r < 8; r++) {
                    float pv = (jj == 0) ? p[r].x : (jj == 1) ? p[r].y
                             : (jj == 2) ? p[r].z : p[r].w;
                    o0[r] += pv * v0;
                    o1[r] += pv * v1;
                }
            }
        }
        __syncwarp();
    }

#pragma unroll
    for (int r = 0; r < 8; r++) {
        float inv = 1.f / l[r];
        size_t base = (size_t)(b * LL + r0 + wq + r) * DIMC + h * HDIM;
        X[base + lane]      = o0[r] * inv;
        X[base + lane + 32] = o1[r] * inv;
    }
}

// ------------------------------- launch --------------------------------------
extern "C" void kernel_launch(void* const* d_in, const int* in_sizes, int n_in,
                              void* d_out, int out_size)
{
    const float* query = (const float*)d_in[0];
    const float* key   = (const float*)d_in[1];
    const float* value = (const float*)d_in[2];
    const float* Wq    = (const float*)d_in[3];
    const float* Wk    = (const float*)d_in[4];
    const float* Wv    = (const float*)d_in[5];
    const float* Wo    = (const float*)d_in[6];
    const float* bo    = (const float*)d_in[7];
    float* out = (float*)d_out;

    float *Qp, *Kp, *Vp, *Xp;
    cudaGetSymbolAddress((void**)&Qp, g_Q);
    cudaGetSymbolAddress((void**)&Kp, g_K);
    cudaGetSymbolAddress((void**)&Vp, g_V);
    cudaGetSymbolAddress((void**)&Xp, g_X);
    __nv_bfloat16 *qh, *ql, *kh, *kl, *vh, *vl, *xh, *xl;
    __nv_bfloat16 *wqh, *wql, *wkh, *wkl, *wvh, *wvl, *woh, *wol;
    cudaGetSymbolAddress((void**)&qh, g_qh);  cudaGetSymbolAddress((void**)&ql, g_ql);
    cudaGetSymbolAddress((void**)&kh, g_kh);  cudaGetSymbolAddress((void**)&kl, g_kl);
    cudaGetSymbolAddress((void**)&vh, g_vh);  cudaGetSymbolAddress((void**)&vl, g_vl);
    cudaGetSymbolAddress((void**)&xh, g_xh);  cudaGetSymbolAddress((void**)&xl, g_xl);
    cudaGetSymbolAddress((void**)&wqh, g_wqh); cudaGetSymbolAddress((void**)&wql, g_wql);
    cudaGetSymbolAddress((void**)&wkh, g_wkh); cudaGetSymbolAddress((void**)&wkl, g_wkl);
    cudaGetSymbolAddress((void**)&wvh, g_wvh); cudaGetSymbolAddress((void**)&wvl, g_wvl);
    cudaGetSymbolAddress((void**)&woh, g_woh); cudaGetSymbolAddress((void**)&wol, g_wol);

    cudaFuncSetAttribute(gemm_mma, cudaFuncAttributeMaxDynamicSharedMemorySize, GEMM_SMEM);
    cudaFuncSetAttribute(attn_k, cudaFuncAttributeMaxDynamicSharedMemorySize, ATTN_SMEM);

    const int nQ4 = BB * LL * DIMC / 4;
    const int nK4 = BB * SS * DIMC / 4;

    split_k<<<nQ4 / 256, 256>>>(query, qh, ql, nQ4);
    split_k<<<nK4 / 256, 256>>>(key,   kh, kl, nK4);
    split_k<<<nK4 / 256, 256>>>(value, vh, vl, nK4);
    dim3 tb(32, 8), tg(32, 32);
    tsplit_k<<<tg, tb>>>(Wq, wqh, wql);
    tsplit_k<<<tg, tb>>>(Wk, wkh, wkl);
    tsplit_k<<<tg, tb>>>(Wv, wvh, wvl);
    tsplit_k<<<tg, tb>>>(Wo, woh, wol);

    gemm_mma<<<dim3(8, 16), 256, GEMM_SMEM>>>(qh, ql, wqh, wql, nullptr, Qp);
    gemm_mma<<<dim3(8, 32), 256, GEMM_SMEM>>>(kh, kl, wkh, wkl, nullptr, Kp);
    gemm_mma<<<dim3(8, 32), 256, GEMM_SMEM>>>(vh, vl, wvh, wvl, nullptr, Vp);

    attn_k<<<dim3(LL / 64, BB * NHEADS), 256, ATTN_SMEM>>>(Qp, Kp, Vp, Xp);

    split_k<<<nQ4 / 256, 256>>>(Xp, xh, xl, nQ4);
    gemm_mma<<<dim3(8, 16), 256, GEMM_SMEM>>>(xh, xl, woh, wol, bo, out);
}

// round 4
// speedup vs baseline: 3.7003x; 1.4571x over previous
#include <cuda_runtime.h>
#include <cuda_bf16.h>
#include <cstdint>
#include <math.h>

#define DIMC   1024
#define NHEADS 16
#define HDIM   64
#define BB     2
#define LL     1024
#define SS     2048
#define QSCALE 0.125f

// ------------------------- device scratch (bf16 hi/lo pairs) -----------------
// input activations (split)
__device__ __nv_bfloat16 g_qih[BB * LL * DIMC], g_qil[BB * LL * DIMC];
__device__ __nv_bfloat16 g_kih[BB * SS * DIMC], g_kil[BB * SS * DIMC];
__device__ __nv_bfloat16 g_vih[BB * SS * DIMC], g_vil[BB * SS * DIMC];
// projected Q,K,V (split, Q pre-scaled)
__device__ __nv_bfloat16 g_qh[BB * LL * DIMC], g_ql[BB * LL * DIMC];
__device__ __nv_bfloat16 g_kh[BB * SS * DIMC], g_kl[BB * SS * DIMC];
__device__ __nv_bfloat16 g_vh[BB * SS * DIMC], g_vl[BB * SS * DIMC];
// attention output (split)
__device__ __nv_bfloat16 g_xh[BB * LL * DIMC], g_xl[BB * LL * DIMC];
// weights transposed+split
__device__ __nv_bfloat16 g_wqh[DIMC * DIMC], g_wql[DIMC * DIMC];
__device__ __nv_bfloat16 g_wkh[DIMC * DIMC], g_wkl[DIMC * DIMC];
__device__ __nv_bfloat16 g_wvh[DIMC * DIMC], g_wvl[DIMC * DIMC];
__device__ __nv_bfloat16 g_woh[DIMC * DIMC], g_wol[DIMC * DIMC];

// ------------------------- split kernels ------------------------------------
__global__ void split_k(const float* __restrict__ X,
                        __nv_bfloat16* __restrict__ H,
                        __nv_bfloat16* __restrict__ L, int n4)
{
    int i = blockIdx.x * 256 + threadIdx.x;
    if (i >= n4) return;
    float4 x = reinterpret_cast<const float4*>(X)[i];
    __nv_bfloat16 h0 = __float2bfloat16(x.x);
    __nv_bfloat16 h1 = __float2bfloat16(x.y);
    __nv_bfloat16 h2 = __float2bfloat16(x.z);
    __nv_bfloat16 h3 = __float2bfloat16(x.w);
    __nv_bfloat16 l0 = __float2bfloat16(x.x - __bfloat162float(h0));
    __nv_bfloat16 l1 = __float2bfloat16(x.y - __bfloat162float(h1));
    __nv_bfloat16 l2 = __float2bfloat16(x.z - __bfloat162float(h2));
    __nv_bfloat16 l3 = __float2bfloat16(x.w - __bfloat162float(h3));
    reinterpret_cast<__nv_bfloat162*>(H)[2 * i + 0] = __nv_bfloat162(h0, h1);
    reinterpret_cast<__nv_bfloat162*>(H)[2 * i + 1] = __nv_bfloat162(h2, h3);
    reinterpret_cast<__nv_bfloat162*>(L)[2 * i + 0] = __nv_bfloat162(l0, l1);
    reinterpret_cast<__nv_bfloat162*>(L)[2 * i + 1] = __nv_bfloat162(l2, l3);
}

__global__ void tsplit_k(const float* __restrict__ W,
                         __nv_bfloat16* __restrict__ Th,
                         __nv_bfloat16* __restrict__ Tl)
{
    __shared__ float t[32][33];
    const int bx = blockIdx.x * 32;  // n
    const int by = blockIdx.y * 32;  // k
    for (int i = threadIdx.y; i < 32; i += 8)
        t[i][threadIdx.x] = W[(size_t)(by + i) * DIMC + bx + threadIdx.x];
    __syncthreads();
    for (int i = threadIdx.y; i < 32; i += 8) {
        int n = bx + i, k = by + threadIdx.x;
        float x = t[threadIdx.x][i];
        __nv_bfloat16 h = __float2bfloat16(x);
        Th[(size_t)n * DIMC + k] = h;
        Tl[(size_t)n * DIMC + k] = __float2bfloat16(x - __bfloat162float(h));
    }
}

// ------------------------- bf16 HMMA helpers ---------------------------------
__device__ __forceinline__ void mma16816(float* d, const uint32_t* a, const uint32_t* b)
{
    asm volatile(
        "mma.sync.aligned.m16n8k16.row.col.f32.bf16.bf16.f32 "
        "{%0,%1,%2,%3}, {%4,%5,%6,%7}, {%8,%9}, {%0,%1,%2,%3};"
        : "+f"(d[0]), "+f"(d[1]), "+f"(d[2]), "+f"(d[3])
        : "r"(a[0]), "r"(a[1]), "r"(a[2]), "r"(a[3]), "r"(b[0]), "r"(b[1]));
}

__device__ __forceinline__ uint32_t pack_bf16x2(float a, float b) {
    __nv_bfloat162 h = __floats2bfloat162_rn(a, b);
    return *reinterpret_cast<uint32_t*>(&h);
}

// ------------------------- HMMA GEMM core -------------------------------------
#define SROW 72
#define SMAT (128 * SROW)
#define SSTAGE (4 * SMAT)
#define GEMM_SMEM (2 * SSTAGE * 2)

template <int B16OUT>
__device__ __forceinline__ void gemm_body(
    const __nv_bfloat16* __restrict__ Ah, const __nv_bfloat16* __restrict__ Al,
    const __nv_bfloat16* __restrict__ Bh, const __nv_bfloat16* __restrict__ Bl,
    const float* __restrict__ bias, float scale,
    float* __restrict__ C, __nv_bfloat16* __restrict__ Ch, __nv_bfloat16* __restrict__ Cl)
{
    extern __shared__ __align__(16) __nv_bfloat16 sm[];

    const int tid  = threadIdx.x;
    const int lane = tid & 31;
    const int w    = tid >> 5;
    const int wm   = w >> 2;
    const int wn   = w & 3;
    const int bm   = blockIdx.y * 128;
    const int bn   = blockIdx.x * 128;

    float acc[4][4][4];
#pragma unroll
    for (int i = 0; i < 4; i++)
#pragma unroll
        for (int j = 0; j < 4; j++)
#pragma unroll
            for (int c = 0; c < 4; c++) acc[i][j][c] = 0.f;

    auto load_chunk = [&](int s, int kc) {
        __nv_bfloat16* dst = sm + s * SSTAGE;
        const __nv_bfloat16* srcA[2] = {Ah, Al};
        const __nv_bfloat16* srcB[2] = {Bh, Bl};
#pragma unroll
        for (int m = 0; m < 2; m++)
#pragma unroll
            for (int it = 0; it < 4; it++) {
                int idx = tid + it * 256;
                int r = idx >> 3, seg = idx & 7;
                *reinterpret_cast<int4*>(dst + m * SMAT + r * SROW + seg * 8) =
                    *reinterpret_cast<const int4*>(srcA[m] + (size_t)(bm + r) * DIMC + kc + seg * 8);
            }
#pragma unroll
        for (int m = 0; m < 2; m++)
#pragma unroll
            for (int it = 0; it < 4; it++) {
                int idx = tid + it * 256;
                int r = idx >> 3, seg = idx & 7;
                *reinterpret_cast<int4*>(dst + (2 + m) * SMAT + r * SROW + seg * 8) =
                    *reinterpret_cast<const int4*>(srcB[m] + (size_t)(bn + r) * DIMC + kc + seg * 8);
            }
    };

    load_chunk(0, 0);
    __syncthreads();

    const int ar = lane >> 2;
    const int ac = (lane & 3) * 2;

    for (int ch = 0; ch < 16; ch++) {
        const int cur = ch & 1;
        if (ch < 15) load_chunk(cur ^ 1, (ch + 1) * 64);

        const __nv_bfloat16* Ahs = sm + cur * SSTAGE;
        const __nv_bfloat16* Als = Ahs + SMAT;
        const __nv_bfloat16* Bhs = Ahs + 2 * SMAT;
        const __nv_bfloat16* Bls = Ahs + 3 * SMAT;

#pragma unroll
        for (int kk = 0; kk < 4; kk++) {
            const int k0 = kk * 16;
            uint32_t ah[4][4], al[4][4], bh[4][2], bl[4][2];
#pragma unroll
            for (int i = 0; i < 4; i++) {
                const __nv_bfloat16* pa = Ahs + (wm * 64 + i * 16 + ar) * SROW + k0 + ac;
                ah[i][0] = *reinterpret_cast<const uint32_t*>(pa);
                ah[i][1] = *reinterpret_cast<const uint32_t*>(pa + 8 * SROW);
                ah[i][2] = *reinterpret_cast<const uint32_t*>(pa + 8);
                ah[i][3] = *reinterpret_cast<const uint32_t*>(pa + 8 * SROW + 8);
                const __nv_bfloat16* pl = Als + (wm * 64 + i * 16 + ar) * SROW + k0 + ac;
                al[i][0] = *reinterpret_cast<const uint32_t*>(pl);
                al[i][1] = *reinterpret_cast<const uint32_t*>(pl + 8 * SROW);
                al[i][2] = *reinterpret_cast<const uint32_t*>(pl + 8);
                al[i][3] = *reinterpret_cast<const uint32_t*>(pl + 8 * SROW + 8);
            }
#pragma unroll
            for (int j = 0; j < 4; j++) {
                const __nv_bfloat16* pb = Bhs + (wn * 32 + j * 8 + ar) * SROW + k0 + ac;
                bh[j][0] = *reinterpret_cast<const uint32_t*>(pb);
                bh[j][1] = *reinterpret_cast<const uint32_t*>(pb + 8);
                const __nv_bfloat16* pc = Bls + (wn * 32 + j * 8 + ar) * SROW + k0 + ac;
                bl[j][0] = *reinterpret_cast<const uint32_t*>(pc);
                bl[j][1] = *reinterpret_cast<const uint32_t*>(pc + 8);
            }
#pragma unroll
            for (int i = 0; i < 4; i++)
#pragma unroll
                for (int j = 0; j < 4; j++) {
                    mma16816(acc[i][j], ah[i], bh[j]);
                    mma16816(acc[i][j], ah[i], bl[j]);
                    mma16816(acc[i][j], al[i], bh[j]);
                }
        }
        __syncthreads();
    }

#pragma unroll
    for (int j = 0; j < 4; j++) {
        const int col = bn + wn * 32 + j * 8 + (lane & 3) * 2;
        float b0 = 0.f, b1 = 0.f;
        if (!B16OUT && bias) { b0 = bias[col]; b1 = bias[col + 1]; }
#pragma unroll
        for (int i = 0; i < 4; i++) {
            const int row = bm + wm * 64 + i * 16 + (lane >> 2);
            if (B16OUT) {
#pragma unroll
                for (int half = 0; half < 2; half++) {
                    float v0 = acc[i][j][half * 2 + 0] * scale;
                    float v1 = acc[i][j][half * 2 + 1] * scale;
                    __nv_bfloat162 hh = __floats2bfloat162_rn(v0, v1);
                    __nv_bfloat162 ll = __floats2bfloat162_rn(
                        v0 - __bfloat162float(hh.x), v1 - __bfloat162float(hh.y));
                    size_t off = (size_t)(row + half * 8) * DIMC + col;
                    *reinterpret_cast<uint32_t*>(Ch + off) = *reinterpret_cast<uint32_t*>(&hh);
                    *reinterpret_cast<uint32_t*>(Cl + off) = *reinterpret_cast<uint32_t*>(&ll);
                }
            } else {
                float2 v;
                v.x = acc[i][j][0] + b0;
                v.y = acc[i][j][1] + b1;
                *reinterpret_cast<float2*>(&C[(size_t)row * DIMC + col]) = v;
                v.x = acc[i][j][2] + b0;
                v.y = acc[i][j][3] + b1;
                *reinterpret_cast<float2*>(&C[(size_t)(row + 8) * DIMC + col]) = v;
            }
        }
    }
}

__global__ void __launch_bounds__(256, 1)
gemm_mma_f32(const __nv_bfloat16* __restrict__ Ah, const __nv_bfloat16* __restrict__ Al,
             const __nv_bfloat16* __restrict__ Bh, const __nv_bfloat16* __restrict__ Bl,
             const float* __restrict__ bias, float* __restrict__ C)
{
    gemm_body<0>(Ah, Al, Bh, Bl, bias, 1.f, C, nullptr, nullptr);
}

__global__ void __launch_bounds__(256, 1)
gemm_mma_b16(const __nv_bfloat16* __restrict__ Ah, const __nv_bfloat16* __restrict__ Al,
             const __nv_bfloat16* __restrict__ Bh, const __nv_bfloat16* __restrict__ Bl,
             float scale, __nv_bfloat16* __restrict__ Ch, __nv_bfloat16* __restrict__ Cl)
{
    gemm_body<1>(Ah, Al, Bh, Bl, nullptr, scale, nullptr, Ch, Cl);
}

// ------------------------- HMMA flash attention -------------------------------
// CTA: 128 q-rows x 1 head. 8 warps, each warp: 16 rows x 64 keys/dims.
#define ATT_KS 72
#define ATT_VS 66

__global__ void __launch_bounds__(256, 1)
attn_mma(const __nv_bfloat16* __restrict__ Qh, const __nv_bfloat16* __restrict__ Ql,
         const __nv_bfloat16* __restrict__ Kh, const __nv_bfloat16* __restrict__ Kl,
         const __nv_bfloat16* __restrict__ Vh, const __nv_bfloat16* __restrict__ Vl,
         __nv_bfloat16* __restrict__ Xh, __nv_bfloat16* __restrict__ Xl)
{
    __shared__ __nv_bfloat16 Ksh[64 * ATT_KS], Ksl[64 * ATT_KS];
    __shared__ __nv_bfloat16 Vth[64 * ATT_VS], Vtl[64 * ATT_VS];

    const int tid = threadIdx.x, lane = tid & 31, w = tid >> 5;
    const int b = blockIdx.y >> 4, h = blockIdx.y & 15;
    const int r0 = blockIdx.x * 128;
    const int qr = lane >> 2;
    const int qc = (lane & 3) * 2;

    // Q fragments, held in registers for the whole loop
    uint32_t qfh[4][4], qfl[4][4];
#pragma unroll
    for (int kk = 0; kk < 4; kk++) {
#pragma unroll
        for (int r = 0; r < 4; r++) {
            int row = r0 + w * 16 + qr + (r & 1) * 8;
            int col = h * HDIM + kk * 16 + qc + (r >> 1) * 8;
            size_t off = (size_t)(b * LL + row) * DIMC + col;
            qfh[kk][r] = *reinterpret_cast<const uint32_t*>(Qh + off);
            qfl[kk][r] = *reinterpret_cast<const uint32_t*>(Ql + off);
        }
    }

    float m0 = -INFINITY, m1 = -INFINITY, l0 = 0.f, l1 = 0.f;
    float o[8][4];
#pragma unroll
    for (int j = 0; j < 8; j++)
#pragma unroll
        for (int c = 0; c < 4; c++) o[j][c] = 0.f;

    for (int s0 = 0; s0 < SS; s0 += 64) {
        __syncthreads();
        // stage K hi/lo, key-major (coalesced)
#pragma unroll
        for (int i = 0; i < 2; i++) {
            int idx = tid + i * 256;
            int key = idx >> 3, seg = idx & 7;
            size_t g = (size_t)(b * SS + s0 + key) * DIMC + h * HDIM + seg * 8;
            *reinterpret_cast<int4*>(Ksh + key * ATT_KS + seg * 8) =
                *reinterpret_cast<const int4*>(Kh + g);
            *reinterpret_cast<int4*>(Ksl + key * ATT_KS + seg * 8) =
                *reinterpret_cast<const int4*>(Kl + g);
        }
        // stage V transposed [dim][key], seg-major mapping
#pragma unroll
        for (int i = 0; i < 2; i++) {
            int idx = tid + i * 256;
            int seg = idx >> 6, key = idx & 63;
            size_t g = (size_t)(b * SS + s0 + key) * DIMC + h * HDIM + seg * 8;
            int4 vh4 = *reinterpret_cast<const int4*>(Vh + g);
            int4 vl4 = *reinterpret_cast<const int4*>(Vl + g);
            const __nv_bfloat16* ph = reinterpret_cast<const __nv_bfloat16*>(&vh4);
            const __nv_bfloat16* pl = reinterpret_cast<const __nv_bfloat16*>(&vl4);
#pragma unroll
            for (int jj = 0; jj < 8; jj++) {
                Vth[(seg * 8 + jj) * ATT_VS + key] = ph[jj];
                Vtl[(seg * 8 + jj) * ATT_VS + key] = pl[jj];
            }
        }
        __syncthreads();

        // ---- scores: S = Q K^T  (3 products) ----
        float sc[8][4];
#pragma unroll
        for (int j = 0; j < 8; j++)
#pragma unroll
            for (int c = 0; c < 4; c++) sc[j][c] = 0.f;

#pragma unroll
        for (int kk = 0; kk < 4; kk++) {
#pragma unroll
            for (int jn = 0; jn < 8; jn++) {
                const __nv_bfloat16* pbh = Ksh + (jn * 8 + qr) * ATT_KS + kk * 16 + qc;
                const __nv_bfloat16* pbl = Ksl + (jn * 8 + qr) * ATT_KS + kk * 16 + qc;
                uint32_t bh[2], bl[2];
                bh[0] = *reinterpret_cast<const uint32_t*>(pbh);
                bh[1] = *reinterpret_cast<const uint32_t*>(pbh + 8);
                bl[0] = *reinterpret_cast<const uint32_t*>(pbl);
                bl[1] = *reinterpret_cast<const uint32_t*>(pbl + 8);
                mma16816(sc[jn], qfh[kk], bh);
                mma16816(sc[jn], qfh[kk], bl);
                mma16816(sc[jn], qfl[kk], bh);
            }
        }

        // ---- online softmax (rows qr and qr+8) ----
        float r0max = -INFINITY, r1max = -INFINITY;
#pragma unroll
        for (int j = 0; j < 8; j++) {
            r0max = fmaxf(r0max, fmaxf(sc[j][0], sc[j][1]));
            r1max = fmaxf(r1max, fmaxf(sc[j][2], sc[j][3]));
        }
        r0max = fmaxf(r0max, __shfl_xor_sync(0xffffffffu, r0max, 1));
        r0max = fmaxf(r0max, __shfl_xor_sync(0xffffffffu, r0max, 2));
        r1max = fmaxf(r1max, __shfl_xor_sync(0xffffffffu, r1max, 1));
        r1max = fmaxf(r1max, __shfl_xor_sync(0xffffffffu, r1max, 2));
        float mn0 = fmaxf(m0, r0max), mn1 = fmaxf(m1, r1max);
        float c0 = __expf(m0 - mn0), c1 = __expf(m1 - mn1);
        m0 = mn0; m1 = mn1;

        float ps0 = 0.f, ps1 = 0.f;
#pragma unroll
        for (int j = 0; j < 8; j++) {
            sc[j][0] = __expf(sc[j][0] - mn0);
            sc[j][1] = __expf(sc[j][1] - mn0);
            sc[j][2] = __expf(sc[j][2] - mn1);
            sc[j][3] = __expf(sc[j][3] - mn1);
            ps0 += sc[j][0] + sc[j][1];
            ps1 += sc[j][2] + sc[j][3];
        }
        ps0 += __shfl_xor_sync(0xffffffffu, ps0, 1);
        ps0 += __shfl_xor_sync(0xffffffffu, ps0, 2);
        ps1 += __shfl_xor_sync(0xffffffffu, ps1, 1);
        ps1 += __shfl_xor_sync(0xffffffffu, ps1, 2);
        l0 = l0 * c0 + ps0;
        l1 = l1 * c1 + ps1;
#pragma unroll
        for (int j = 0; j < 8; j++) {
            o[j][0] *= c0; o[j][1] *= c0;
            o[j][2] *= c1; o[j][3] *= c1;
        }

        // ---- O += P V (3 products), P fragments built in registers ----
#pragma unroll
        for (int kk = 0; kk < 4; kk++) {
            uint32_t pah[4], pal[4];
            {
                float p00 = sc[2 * kk][0],     p01 = sc[2 * kk][1];
                float p10 = sc[2 * kk][2],     p11 = sc[2 * kk][3];
                float p20 = sc[2 * kk + 1][0], p21 = sc[2 * kk + 1][1];
                float p30 = sc[2 * kk + 1][2], p31 = sc[2 * kk + 1][3];
                __nv_bfloat162 t;
                t = __floats2bfloat162_rn(p00, p01); pah[0] = *reinterpret_cast<uint32_t*>(&t);
                pal[0] = pack_bf16x2(p00 - __bfloat162float(t.x), p01 - __bfloat162float(t.y));
                t = __floats2bfloat162_rn(p10, p11); pah[1] = *reinterpret_cast<uint32_t*>(&t);
                pal[1] = pack_bf16x2(p10 - __bfloat162float(t.x), p11 - __bfloat162float(t.y));
                t = __floats2bfloat162_rn(p20, p21); pah[2] = *reinterpret_cast<uint32_t*>(&t);
                pal[2] = pack_bf16x2(p20 - __bfloat162float(t.x), p21 - __bfloat162float(t.y));
                t = __floats2bfloat162_rn(p30, p31); pah[3] = *reinterpret_cast<uint32_t*>(&t);
                pal[3] = pack_bf16x2(p30 - __bfloat162float(t.x), p31 - __bfloat162float(t.y));
            }
#pragma unroll
            for (int jd = 0; jd < 8; jd++) {
                const __nv_bfloat16* pvh = Vth + (jd * 8 + qr) * ATT_VS + kk * 16 + qc;
                const __nv_bfloat16* pvl = Vtl + (jd * 8 + qr) * ATT_VS + kk * 16 + qc;
                uint32_t vh[2], vl[2];
                vh[0] = *reinterpret_cast<const uint32_t*>(pvh);
                vh[1] = *reinterpret_cast<const uint32_t*>(pvh + 8);
                vl[0] = *reinterpret_cast<const uint32_t*>(pvl);
                vl[1] = *reinterpret_cast<const uint32_t*>(pvl + 8);
                mma16816(o[jd], pah, vh);
                mma16816(o[jd], pah, vl);
                mma16816(o[jd], pal, vh);
            }
        }
    }

    // ---- epilogue: normalize, split to bf16 hi/lo, store ----
    float i0 = 1.f / l0, i1 = 1.f / l1;
#pragma unroll
    for (int jd = 0; jd < 8; jd++) {
        int col = h * HDIM + jd * 8 + qc;
        int row0 = r0 + w * 16 + qr;
        float v0 = o[jd][0] * i0, v1 = o[jd][1] * i0;
        __nv_bfloat162 hh = __floats2bfloat162_rn(v0, v1);
        __nv_bfloat162 ll = __floats2bfloat162_rn(
            v0 - __bfloat162float(hh.x), v1 - __bfloat162float(hh.y));
        size_t off = (size_t)(b * LL + row0) * DIMC + col;
        *reinterpret_cast<uint32_t*>(Xh + off) = *reinterpret_cast<uint32_t*>(&hh);
        *reinterpret_cast<uint32_t*>(Xl + off) = *reinterpret_cast<uint32_t*>(&ll);

        float v2 = o[jd][2] * i1, v3 = o[jd][3] * i1;
        hh = __floats2bfloat162_rn(v2, v3);
        ll = __floats2bfloat162_rn(v2 - __bfloat162float(hh.x), v3 - __bfloat162float(hh.y));
        off = (size_t)(b * LL + row0 + 8) * DIMC + col;
        *reinterpret_cast<uint32_t*>(Xh + off) = *reinterpret_cast<uint32_t*>(&hh);
        *reinterpret_cast<uint32_t*>(Xl + off) = *reinterpret_cast<uint32_t*>(&ll);
    }
}

// ------------------------------- launch --------------------------------------
extern "C" void kernel_launch(void* const* d_in, const int* in_sizes, int n_in,
                              void* d_out, int out_size)
{
    const float* query = (const float*)d_in[0];
    const float* key   = (const float*)d_in[1];
    const float* value = (const float*)d_in[2];
    const float* Wq    = (const float*)d_in[3];
    const float* Wk    = (const float*)d_in[4];
    const float* Wv    = (const float*)d_in[5];
    const float* Wo    = (const float*)d_in[6];
    const float* bo    = (const float*)d_in[7];
    float* out = (float*)d_out;

    __nv_bfloat16 *qih, *qil, *kih, *kil, *vih, *vil;
    __nv_bfloat16 *qh, *ql, *kh, *kl, *vh, *vl, *xh, *xl;
    __nv_bfloat16 *wqh, *wql, *wkh, *wkl, *wvh, *wvl, *woh, *wol;
    cudaGetSymbolAddress((void**)&qih, g_qih); cudaGetSymbolAddress((void**)&qil, g_qil);
    cudaGetSymbolAddress((void**)&kih, g_kih); cudaGetSymbolAddress((void**)&kil, g_kil);
    cudaGetSymbolAddress((void**)&vih, g_vih); cudaGetSymbolAddress((void**)&vil, g_vil);
    cudaGetSymbolAddress((void**)&qh, g_qh);   cudaGetSymbolAddress((void**)&ql, g_ql);
    cudaGetSymbolAddress((void**)&kh, g_kh);   cudaGetSymbolAddress((void**)&kl, g_kl);
    cudaGetSymbolAddress((void**)&vh, g_vh);   cudaGetSymbolAddress((void**)&vl, g_vl);
    cudaGetSymbolAddress((void**)&xh, g_xh);   cudaGetSymbolAddress((void**)&xl, g_xl);
    cudaGetSymbolAddress((void**)&wqh, g_wqh); cudaGetSymbolAddress((void**)&wql, g_wql);
    cudaGetSymbolAddress((void**)&wkh, g_wkh); cudaGetSymbolAddress((void**)&wkl, g_wkl);
    cudaGetSymbolAddress((void**)&wvh, g_wvh); cudaGetSymbolAddress((void**)&wvl, g_wvl);
    cudaGetSymbolAddress((void**)&woh, g_woh); cudaGetSymbolAddress((void**)&wol, g_wol);

    cudaFuncSetAttribute(gemm_mma_f32, cudaFuncAttributeMaxDynamicSharedMemorySize, GEMM_SMEM);
    cudaFuncSetAttribute(gemm_mma_b16, cudaFuncAttributeMaxDynamicSharedMemorySize, GEMM_SMEM);

    const int nQ4 = BB * LL * DIMC / 4;
    const int nK4 = BB * SS * DIMC / 4;

    split_k<<<nQ4 / 256, 256>>>(query, qih, qil, nQ4);
    split_k<<<nK4 / 256, 256>>>(key,   kih, kil, nK4);
    split_k<<<nK4 / 256, 256>>>(value, vih, vil, nK4);
    dim3 tb(32, 8), tg(32, 32);
    tsplit_k<<<tg, tb>>>(Wq, wqh, wql);
    tsplit_k<<<tg, tb>>>(Wk, wkh, wkl);
    tsplit_k<<<tg, tb>>>(Wv, wvh, wvl);
    tsplit_k<<<tg, tb>>>(Wo, woh, wol);

    // projections -> bf16 hi/lo (Q pre-scaled by 1/sqrt(HDIM))
    gemm_mma_b16<<<dim3(8, 16), 256, GEMM_SMEM>>>(qih, qil, wqh, wql, QSCALE, qh, ql);
    gemm_mma_b16<<<dim3(8, 32), 256, GEMM_SMEM>>>(kih, kil, wkh, wkl, 1.f, kh, kl);
    gemm_mma_b16<<<dim3(8, 32), 256, GEMM_SMEM>>>(vih, vil, wvh, wvl, 1.f, vh, vl);

    // tensor-core flash attention
    attn_mma<<<dim3(LL / 128, BB * NHEADS), 256>>>(qh, ql, kh, kl, vh, vl, xh, xl);

    // output projection (+bias) -> fp32 out
    gemm_mma_f32<<<dim3(8, 16), 256, GEMM_SMEM>>>(xh, xl, woh, wol, bo, out);
}

// round 5
// speedup vs baseline: 3.9914x; 1.0787x over previous
#include <cuda_runtime.h>
#include <cuda_bf16.h>
#include <cstdint>
#include <math.h>

#define DIMC   1024
#define NHEADS 16
#define HDIM   64
#define BB     2
#define LL     1024
#define SS     2048
#define QSCALE 0.125f

// ------------------------- device scratch (bf16 hi/lo pairs) -----------------
__device__ __nv_bfloat16 g_qih[BB * LL * DIMC], g_qil[BB * LL * DIMC];
__device__ __nv_bfloat16 g_kih[BB * SS * DIMC], g_kil[BB * SS * DIMC];
__device__ __nv_bfloat16 g_vih[BB * SS * DIMC], g_vil[BB * SS * DIMC];
__device__ __nv_bfloat16 g_qh[BB * LL * DIMC], g_ql[BB * LL * DIMC];
__device__ __nv_bfloat16 g_kh[BB * SS * DIMC], g_kl[BB * SS * DIMC];
__device__ __nv_bfloat16 g_vh[BB * SS * DIMC], g_vl[BB * SS * DIMC];
__device__ __nv_bfloat16 g_xh[BB * LL * DIMC], g_xl[BB * LL * DIMC];
__device__ __nv_bfloat16 g_wqh[DIMC * DIMC], g_wql[DIMC * DIMC];
__device__ __nv_bfloat16 g_wkh[DIMC * DIMC], g_wkl[DIMC * DIMC];
__device__ __nv_bfloat16 g_wvh[DIMC * DIMC], g_wvl[DIMC * DIMC];
__device__ __nv_bfloat16 g_woh[DIMC * DIMC], g_wol[DIMC * DIMC];

// device-side pointer tables for fused kernels
__device__ const float*         c_splitSrc[3];
__device__ __nv_bfloat16*       c_splitH[3];
__device__ __nv_bfloat16*       c_splitL[3];
__device__ const float*         c_wSrc[4];
__device__ __nv_bfloat16*       c_wH[4];
__device__ __nv_bfloat16*       c_wL[4];
__device__ const __nv_bfloat16* c_gAh[3];
__device__ const __nv_bfloat16* c_gAl[3];
__device__ const __nv_bfloat16* c_gBh[3];
__device__ const __nv_bfloat16* c_gBl[3];
__device__ __nv_bfloat16*       c_gCh[3];
__device__ __nv_bfloat16*       c_gCl[3];

// ------------------------- cp.async helpers ----------------------------------
__device__ __forceinline__ void cp_async16(void* smem_dst, const void* gmem_src) {
    uint32_t s;
    asm("{ .reg .u64 t; cvta.to.shared.u64 t, %1; cvt.u32.u64 %0, t; }"
        : "=r"(s) : "l"(smem_dst));
    asm volatile("cp.async.cg.shared.global [%0], [%1], 16;" :: "r"(s), "l"(gmem_src));
}
__device__ __forceinline__ void cp_commit() {
    asm volatile("cp.async.commit_group;" ::: "memory");
}
__device__ __forceinline__ void cp_wait_all() {
    asm volatile("cp.async.wait_group 0;" ::: "memory");
}

// ------------------------- fused split kernels --------------------------------
// z=0: query (nQ4), z=1: key, z=2: value (nK4)
__global__ void split_all_k()
{
    const int z = blockIdx.z;
    const int n4 = (z == 0) ? (BB * LL * DIMC / 4) : (BB * SS * DIMC / 4);
    int i = blockIdx.x * 256 + threadIdx.x;
    if (i >= n4) return;
    const float* X = c_splitSrc[z];
    __nv_bfloat16* H = c_splitH[z];
    __nv_bfloat16* L = c_splitL[z];
    float4 x = reinterpret_cast<const float4*>(X)[i];
    __nv_bfloat16 h0 = __float2bfloat16(x.x);
    __nv_bfloat16 h1 = __float2bfloat16(x.y);
    __nv_bfloat16 h2 = __float2bfloat16(x.z);
    __nv_bfloat16 h3 = __float2bfloat16(x.w);
    __nv_bfloat16 l0 = __float2bfloat16(x.x - __bfloat162float(h0));
    __nv_bfloat16 l1 = __float2bfloat16(x.y - __bfloat162float(h1));
    __nv_bfloat16 l2 = __float2bfloat16(x.z - __bfloat162float(h2));
    __nv_bfloat16 l3 = __float2bfloat16(x.w - __bfloat162float(h3));
    reinterpret_cast<__nv_bfloat162*>(H)[2 * i + 0] = __nv_bfloat162(h0, h1);
    reinterpret_cast<__nv_bfloat162*>(H)[2 * i + 1] = __nv_bfloat162(h2, h3);
    reinterpret_cast<__nv_bfloat162*>(L)[2 * i + 0] = __nv_bfloat162(l0, l1);
    reinterpret_cast<__nv_bfloat162*>(L)[2 * i + 1] = __nv_bfloat162(l2, l3);
}

__global__ void tsplit_all_k()
{
    __shared__ float t[32][33];
    const int z = blockIdx.z;
    const float* W = c_wSrc[z];
    __nv_bfloat16* Th = c_wH[z];
    __nv_bfloat16* Tl = c_wL[z];
    const int bx = blockIdx.x * 32;
    const int by = blockIdx.y * 32;
    for (int i = threadIdx.y; i < 32; i += 8)
        t[i][threadIdx.x] = W[(size_t)(by + i) * DIMC + bx + threadIdx.x];
    __syncthreads();
    for (int i = threadIdx.y; i < 32; i += 8) {
        int n = bx + i, k = by + threadIdx.x;
        float x = t[threadIdx.x][i];
        __nv_bfloat16 h = __float2bfloat16(x);
        Th[(size_t)n * DIMC + k] = h;
        Tl[(size_t)n * DIMC + k] = __float2bfloat16(x - __bfloat162float(h));
    }
}

// ------------------------- bf16 HMMA helpers ---------------------------------
__device__ __forceinline__ void mma16816(float* d, const uint32_t* a, const uint32_t* b)
{
    asm volatile(
        "mma.sync.aligned.m16n8k16.row.col.f32.bf16.bf16.f32 "
        "{%0,%1,%2,%3}, {%4,%5,%6,%7}, {%8,%9}, {%0,%1,%2,%3};"
        : "+f"(d[0]), "+f"(d[1]), "+f"(d[2]), "+f"(d[3])
        : "r"(a[0]), "r"(a[1]), "r"(a[2]), "r"(a[3]), "r"(b[0]), "r"(b[1]));
}
__device__ __forceinline__ uint32_t pack_bf16x2(float a, float b) {
    __nv_bfloat162 h = __floats2bfloat162_rn(a, b);
    return *reinterpret_cast<uint32_t*>(&h);
}

// ------------------------- HMMA GEMM core (cp.async pipeline) -----------------
#define SROW 72
#define SMAT (128 * SROW)
#define SSTAGE (4 * SMAT)
#define GEMM_SMEM (2 * SSTAGE * 2)

template <int B16OUT>
__device__ __forceinline__ void gemm_body(
    const __nv_bfloat16* __restrict__ Ah, const __nv_bfloat16* __restrict__ Al,
    const __nv_bfloat16* __restrict__ Bh, const __nv_bfloat16* __restrict__ Bl,
    const float* __restrict__ bias, float scale,
    float* __restrict__ C, __nv_bfloat16* __restrict__ Ch, __nv_bfloat16* __restrict__ Cl,
    int bm, int bn)
{
    extern __shared__ __align__(16) __nv_bfloat16 sm[];

    const int tid  = threadIdx.x;
    const int lane = tid & 31;
    const int w    = tid >> 5;
    const int wm   = w >> 2;
    const int wn   = w & 3;

    float acc[4][4][4];
#pragma unroll
    for (int i = 0; i < 4; i++)
#pragma unroll
        for (int j = 0; j < 4; j++)
#pragma unroll
            for (int c = 0; c < 4; c++) acc[i][j][c] = 0.f;

    auto cp_chunk = [&](int s, int kc) {
        __nv_bfloat16* dst = sm + s * SSTAGE;
        const __nv_bfloat16* srcA[2] = {Ah, Al};
        const __nv_bfloat16* srcB[2] = {Bh, Bl};
#pragma unroll
        for (int m = 0; m < 2; m++)
#pragma unroll
            for (int it = 0; it < 4; it++) {
                int idx = tid + it * 256;
                int r = idx >> 3, seg = idx & 7;
                cp_async16(dst + m * SMAT + r * SROW + seg * 8,
                           srcA[m] + (size_t)(bm + r) * DIMC + kc + seg * 8);
            }
#pragma unroll
        for (int m = 0; m < 2; m++)
#pragma unroll
            for (int it = 0; it < 4; it++) {
                int idx = tid + it * 256;
                int r = idx >> 3, seg = idx & 7;
                cp_async16(dst + (2 + m) * SMAT + r * SROW + seg * 8,
                           srcB[m] + (size_t)(bn + r) * DIMC + kc + seg * 8);
            }
    };

    cp_chunk(0, 0);
    cp_commit();

    const int ar = lane >> 2;
    const int ac = (lane & 3) * 2;

    for (int ch = 0; ch < 16; ch++) {
        const int cur = ch & 1;
        cp_wait_all();
        __syncthreads();
        if (ch < 15) {
            cp_chunk(cur ^ 1, (ch + 1) * 64);
            cp_commit();
        }

        const __nv_bfloat16* Ahs = sm + cur * SSTAGE;
        const __nv_bfloat16* Als = Ahs + SMAT;
        const __nv_bfloat16* Bhs = Ahs + 2 * SMAT;
        const __nv_bfloat16* Bls = Ahs + 3 * SMAT;

#pragma unroll
        for (int kk = 0; kk < 4; kk++) {
            const int k0 = kk * 16;
            uint32_t ah[4][4], al[4][4], bh[4][2], bl[4][2];
#pragma unroll
            for (int i = 0; i < 4; i++) {
                const __nv_bfloat16* pa = Ahs + (wm * 64 + i * 16 + ar) * SROW + k0 + ac;
                ah[i][0] = *reinterpret_cast<const uint32_t*>(pa);
                ah[i][1] = *reinterpret_cast<const uint32_t*>(pa + 8 * SROW);
                ah[i][2] = *reinterpret_cast<const uint32_t*>(pa + 8);
                ah[i][3] = *reinterpret_cast<const uint32_t*>(pa + 8 * SROW + 8);
                const __nv_bfloat16* pl = Als + (wm * 64 + i * 16 + ar) * SROW + k0 + ac;
                al[i][0] = *reinterpret_cast<const uint32_t*>(pl);
                al[i][1] = *reinterpret_cast<const uint32_t*>(pl + 8 * SROW);
                al[i][2] = *reinterpret_cast<const uint32_t*>(pl + 8);
                al[i][3] = *reinterpret_cast<const uint32_t*>(pl + 8 * SROW + 8);
            }
#pragma unroll
            for (int j = 0; j < 4; j++) {
                const __nv_bfloat16* pb = Bhs + (wn * 32 + j * 8 + ar) * SROW + k0 + ac;
                bh[j][0] = *reinterpret_cast<const uint32_t*>(pb);
                bh[j][1] = *reinterpret_cast<const uint32_t*>(pb + 8);
                const __nv_bfloat16* pc = Bls + (wn * 32 + j * 8 + ar) * SROW + k0 + ac;
                bl[j][0] = *reinterpret_cast<const uint32_t*>(pc);
                bl[j][1] = *reinterpret_cast<const uint32_t*>(pc + 8);
            }
#pragma unroll
            for (int i = 0; i < 4; i++)
#pragma unroll
                for (int j = 0; j < 4; j++) {
                    mma16816(acc[i][j], ah[i], bh[j]);
                    mma16816(acc[i][j], ah[i], bl[j]);
                    mma16816(acc[i][j], al[i], bh[j]);
                }
        }
        __syncthreads();
    }

#pragma unroll
    for (int j = 0; j < 4; j++) {
        const int col = bn + wn * 32 + j * 8 + (lane & 3) * 2;
        float b0 = 0.f, b1 = 0.f;
        if (!B16OUT && bias) { b0 = bias[col]; b1 = bias[col + 1]; }
#pragma unroll
        for (int i = 0; i < 4; i++) {
            const int row = bm + wm * 64 + i * 16 + (lane >> 2);
            if (B16OUT) {
#pragma unroll
                for (int half = 0; half < 2; half++) {
                    float v0 = acc[i][j][half * 2 + 0] * scale;
                    float v1 = acc[i][j][half * 2 + 1] * scale;
                    __nv_bfloat162 hh = __floats2bfloat162_rn(v0, v1);
                    __nv_bfloat162 ll = __floats2bfloat162_rn(
                        v0 - __bfloat162float(hh.x), v1 - __bfloat162float(hh.y));
                    size_t off = (size_t)(row + half * 8) * DIMC + col;
                    *reinterpret_cast<uint32_t*>(Ch + off) = *reinterpret_cast<uint32_t*>(&hh);
                    *reinterpret_cast<uint32_t*>(Cl + off) = *reinterpret_cast<uint32_t*>(&ll);
                }
            } else {
                float2 v;
                v.x = acc[i][j][0] + b0;
                v.y = acc[i][j][1] + b1;
                *reinterpret_cast<float2*>(&C[(size_t)row * DIMC + col]) = v;
                v.x = acc[i][j][2] + b0;
                v.y = acc[i][j][3] + b1;
                *reinterpret_cast<float2*>(&C[(size_t)(row + 8) * DIMC + col]) = v;
            }
        }
    }
}

// fused QKV projection: z=0 Q (16 row-blocks), z=1 K, z=2 V (32 row-blocks)
__global__ void __launch_bounds__(256, 1)
gemm_qkv(void)
{
    const int z = blockIdx.z;
    const int mblocks = (z == 0) ? 16 : 32;
    if (blockIdx.y >= mblocks) return;
    const float scale = (z == 0) ? QSCALE : 1.f;
    gemm_body<1>(c_gAh[z], c_gAl[z], c_gBh[z], c_gBl[z], nullptr, scale,
                 nullptr, c_gCh[z], c_gCl[z], blockIdx.y * 128, blockIdx.x * 128);
}

__global__ void __launch_bounds__(256, 1)
gemm_mma_f32(const __nv_bfloat16* __restrict__ Ah, const __nv_bfloat16* __restrict__ Al,
             const __nv_bfloat16* __restrict__ Bh, const __nv_bfloat16* __restrict__ Bl,
             const float* __restrict__ bias, float* __restrict__ C)
{
    gemm_body<0>(Ah, Al, Bh, Bl, bias, 1.f, C, nullptr, nullptr,
                 blockIdx.y * 128, blockIdx.x * 128);
}

// ------------------------- HMMA flash attention -------------------------------
#define ATT_KS 72
#define ATT_VS 66

__global__ void __launch_bounds__(256, 1)
attn_mma(const __nv_bfloat16* __restrict__ Qh, const __nv_bfloat16* __restrict__ Ql,
         const __nv_bfloat16* __restrict__ Kh, const __nv_bfloat16* __restrict__ Kl,
         const __nv_bfloat16* __restrict__ Vh, const __nv_bfloat16* __restrict__ Vl,
         __nv_bfloat16* __restrict__ Xh, __nv_bfloat16* __restrict__ Xl)
{
    __shared__ __nv_bfloat16 Ksh[64 * ATT_KS], Ksl[64 * ATT_KS];
    __shared__ __nv_bfloat16 Vth[64 * ATT_VS], Vtl[64 * ATT_VS];

    const int tid = threadIdx.x, lane = tid & 31, w = tid >> 5;
    const int b = blockIdx.y >> 4, h = blockIdx.y & 15;
    const int r0 = blockIdx.x * 128;
    const int qr = lane >> 2;
    const int qc = (lane & 3) * 2;

    uint32_t qfh[4][4], qfl[4][4];
#pragma unroll
    for (int kk = 0; kk < 4; kk++) {
#pragma unroll
        for (int r = 0; r < 4; r++) {
            int row = r0 + w * 16 + qr + (r & 1) * 8;
            int col = h * HDIM + kk * 16 + qc + (r >> 1) * 8;
            size_t off = (size_t)(b * LL + row) * DIMC + col;
            qfh[kk][r] = *reinterpret_cast<const uint32_t*>(Qh + off);
            qfl[kk][r] = *reinterpret_cast<const uint32_t*>(Ql + off);
        }
    }

    float m0 = -INFINITY, m1 = -INFINITY, l0 = 0.f, l1 = 0.f;
    float o[8][4];
#pragma unroll
    for (int j = 0; j < 8; j++)
#pragma unroll
        for (int c = 0; c < 4; c++) o[j][c] = 0.f;

    for (int s0 = 0; s0 < SS; s0 += 64) {
        __syncthreads();
#pragma unroll
        for (int i = 0; i < 2; i++) {
            int idx = tid + i * 256;
            int key = idx >> 3, seg = idx & 7;
            size_t g = (size_t)(b * SS + s0 + key) * DIMC + h * HDIM + seg * 8;
            *reinterpret_cast<int4*>(Ksh + key * ATT_KS + seg * 8) =
                *reinterpret_cast<const int4*>(Kh + g);
            *reinterpret_cast<int4*>(Ksl + key * ATT_KS + seg * 8) =
                *reinterpret_cast<const int4*>(Kl + g);
        }
#pragma unroll
        for (int i = 0; i < 2; i++) {
            int idx = tid + i * 256;
            int seg = idx >> 6, key = idx & 63;
            size_t g = (size_t)(b * SS + s0 + key) * DIMC + h * HDIM + seg * 8;
            int4 vh4 = *reinterpret_cast<const int4*>(Vh + g);
            int4 vl4 = *reinterpret_cast<const int4*>(Vl + g);
            const __nv_bfloat16* ph = reinterpret_cast<const __nv_bfloat16*>(&vh4);
            const __nv_bfloat16* pl = reinterpret_cast<const __nv_bfloat16*>(&vl4);
#pragma unroll
            for (int jj = 0; jj < 8; jj++) {
                Vth[(seg * 8 + jj) * ATT_VS + key] = ph[jj];
                Vtl[(seg * 8 + jj) * ATT_VS + key] = pl[jj];
            }
        }
        __syncthreads();

        float sc[8][4];
#pragma unroll
        for (int j = 0; j < 8; j++)
#pragma unroll
            for (int c = 0; c < 4; c++) sc[j][c] = 0.f;

#pragma unroll
        for (int kk = 0; kk < 4; kk++) {
#pragma unroll
            for (int jn = 0; jn < 8; jn++) {
                const __nv_bfloat16* pbh = Ksh + (jn * 8 + qr) * ATT_KS + kk * 16 + qc;
                const __nv_bfloat16* pbl = Ksl + (jn * 8 + qr) * ATT_KS + kk * 16 + qc;
                uint32_t bh[2], bl[2];
                bh[0] = *reinterpret_cast<const uint32_t*>(pbh);
                bh[1] = *reinterpret_cast<const uint32_t*>(pbh + 8);
                bl[0] = *reinterpret_cast<const uint32_t*>(pbl);
                bl[1] = *reinterpret_cast<const uint32_t*>(pbl + 8);
                mma16816(sc[jn], qfh[kk], bh);
                mma16816(sc[jn], qfh[kk], bl);
                mma16816(sc[jn], qfl[kk], bh);
            }
        }

        float r0max = -INFINITY, r1max = -INFINITY;
#pragma unroll
        for (int j = 0; j < 8; j++) {
            r0max = fmaxf(r0max, fmaxf(sc[j][0], sc[j][1]));
            r1max = fmaxf(r1max, fmaxf(sc[j][2], sc[j][3]));
        }
        r0max = fmaxf(r0max, __shfl_xor_sync(0xffffffffu, r0max, 1));
        r0max = fmaxf(r0max, __shfl_xor_sync(0xffffffffu, r0max, 2));
        r1max = fmaxf(r1max, __shfl_xor_sync(0xffffffffu, r1max, 1));
        r1max = fmaxf(r1max, __shfl_xor_sync(0xffffffffu, r1max, 2));
        float mn0 = fmaxf(m0, r0max), mn1 = fmaxf(m1, r1max);
        float c0 = __expf(m0 - mn0), c1 = __expf(m1 - mn1);
        m0 = mn0; m1 = mn1;

        float ps0 = 0.f, ps1 = 0.f;
#pragma unroll
        for (int j = 0; j < 8; j++) {
            sc[j][0] = __expf(sc[j][0] - mn0);
            sc[j][1] = __expf(sc[j][1] - mn0);
            sc[j][2] = __expf(sc[j][2] - mn1);
            sc[j][3] = __expf(sc[j][3] - mn1);
            ps0 += sc[j][0] + sc[j][1];
            ps1 += sc[j][2] + sc[j][3];
        }
        ps0 += __shfl_xor_sync(0xffffffffu, ps0, 1);
        ps0 += __shfl_xor_sync(0xffffffffu, ps0, 2);
        ps1 += __shfl_xor_sync(0xffffffffu, ps1, 1);
        ps1 += __shfl_xor_sync(0xffffffffu, ps1, 2);
        l0 = l0 * c0 + ps0;
        l1 = l1 * c1 + ps1;
#pragma unroll
        for (int j = 0; j < 8; j++) {
            o[j][0] *= c0; o[j][1] *= c0;
            o[j][2] *= c1; o[j][3] *= c1;
        }

#pragma unroll
        for (int kk = 0; kk < 4; kk++) {
            uint32_t pah[4], pal[4];
            {
                float p00 = sc[2 * kk][0],     p01 = sc[2 * kk][1];
                float p10 = sc[2 * kk][2],     p11 = sc[2 * kk][3];
                float p20 = sc[2 * kk + 1][0], p21 = sc[2 * kk + 1][1];
                float p30 = sc[2 * kk + 1][2], p31 = sc[2 * kk + 1][3];
                __nv_bfloat162 t;
                t = __floats2bfloat162_rn(p00, p01); pah[0] = *reinterpret_cast<uint32_t*>(&t);
                pal[0] = pack_bf16x2(p00 - __bfloat162float(t.x), p01 - __bfloat162float(t.y));
                t = __floats2bfloat162_rn(p10, p11); pah[1] = *reinterpret_cast<uint32_t*>(&t);
                pal[1] = pack_bf16x2(p10 - __bfloat162float(t.x), p11 - __bfloat162float(t.y));
                t = __floats2bfloat162_rn(p20, p21); pah[2] = *reinterpret_cast<uint32_t*>(&t);
                pal[2] = pack_bf16x2(p20 - __bfloat162float(t.x), p21 - __bfloat162float(t.y));
                t = __floats2bfloat162_rn(p30, p31); pah[3] = *reinterpret_cast<uint32_t*>(&t);
                pal[3] = pack_bf16x2(p30 - __bfloat162float(t.x), p31 - __bfloat162float(t.y));
            }
#pragma unroll
            for (int jd = 0; jd < 8; jd++) {
                const __nv_bfloat16* pvh = Vth + (jd * 8 + qr) * ATT_VS + kk * 16 + qc;
                const __nv_bfloat16* pvl = Vtl + (jd * 8 + qr) * ATT_VS + kk * 16 + qc;
                uint32_t vh[2], vl[2];
                vh[0] = *reinterpret_cast<const uint32_t*>(pvh);
                vh[1] = *reinterpret_cast<const uint32_t*>(pvh + 8);
                vl[0] = *reinterpret_cast<const uint32_t*>(pvl);
                vl[1] = *reinterpret_cast<const uint32_t*>(pvl + 8);
                mma16816(o[jd], pah, vh);
                mma16816(o[jd], pah, vl);
                mma16816(o[jd], pal, vh);
            }
        }
    }

    float i0 = 1.f / l0, i1 = 1.f / l1;
#pragma unroll
    for (int jd = 0; jd < 8; jd++) {
        int col = h * HDIM + jd * 8 + qc;
        int row0 = r0 + w * 16 + qr;
        float v0 = o[jd][0] * i0, v1 = o[jd][1] * i0;
        __nv_bfloat162 hh = __floats2bfloat162_rn(v0, v1);
        __nv_bfloat162 ll = __floats2bfloat162_rn(
            v0 - __bfloat162float(hh.x), v1 - __bfloat162float(hh.y));
        size_t off = (size_t)(b * LL + row0) * DIMC + col;
        *reinterpret_cast<uint32_t*>(Xh + off) = *reinterpret_cast<uint32_t*>(&hh);
        *reinterpret_cast<uint32_t*>(Xl + off) = *reinterpret_cast<uint32_t*>(&ll);

        float v2 = o[jd][2] * i1, v3 = o[jd][3] * i1;
        hh = __floats2bfloat162_rn(v2, v3);
        ll = __floats2bfloat162_rn(v2 - __bfloat162float(hh.x), v3 - __bfloat162float(hh.y));
        off = (size_t)(b * LL + row0 + 8) * DIMC + col;
        *reinterpret_cast<uint32_t*>(Xh + off) = *reinterpret_cast<uint32_t*>(&hh);
        *reinterpret_cast<uint32_t*>(Xl + off) = *reinterpret_cast<uint32_t*>(&ll);
    }
}

// setup kernel: fill device pointer tables (runs every launch; deterministic)
__global__ void setup_ptrs(const float* query, const float* key, const float* value,
                           const float* Wq, const float* Wk, const float* Wv, const float* Wo)
{
    c_splitSrc[0] = query; c_splitSrc[1] = key; c_splitSrc[2] = value;
    c_splitH[0] = g_qih; c_splitL[0] = g_qil;
    c_splitH[1] = g_kih; c_splitL[1] = g_kil;
    c_splitH[2] = g_vih; c_splitL[2] = g_vil;
    c_wSrc[0] = Wq; c_wSrc[1] = Wk; c_wSrc[2] = Wv; c_wSrc[3] = Wo;
    c_wH[0] = g_wqh; c_wL[0] = g_wql;
    c_wH[1] = g_wkh; c_wL[1] = g_wkl;
    c_wH[2] = g_wvh; c_wL[2] = g_wvl;
    c_wH[3] = g_woh; c_wL[3] = g_wol;
    c_gAh[0] = g_qih; c_gAl[0] = g_qil; c_gBh[0] = g_wqh; c_gBl[0] = g_wql;
    c_gCh[0] = g_qh;  c_gCl[0] = g_ql;
    c_gAh[1] = g_kih; c_gAl[1] = g_kil; c_gBh[1] = g_wkh; c_gBl[1] = g_wkl;
    c_gCh[1] = g_kh;  c_gCl[1] = g_kl;
    c_gAh[2] = g_vih; c_gAl[2] = g_vil; c_gBh[2] = g_wvh; c_gBl[2] = g_wvl;
    c_gCh[2] = g_vh;  c_gCl[2] = g_vl;
}

// ------------------------------- launch --------------------------------------
extern "C" void kernel_launch(void* const* d_in, const int* in_sizes, int n_in,
                              void* d_out, int out_size)
{
    const float* query = (const float*)d_in[0];
    const float* key   = (const float*)d_in[1];
    const float* value = (const float*)d_in[2];
    const float* Wq    = (const float*)d_in[3];
    const float* Wk    = (const float*)d_in[4];
    const float* Wv    = (const float*)d_in[5];
    const float* Wo    = (const float*)d_in[6];
    const float* bo    = (const float*)d_in[7];
    float* out = (float*)d_out;

    __nv_bfloat16 *qh, *ql, *kh, *kl, *vh, *vl, *xh, *xl, *woh, *wol;
    cudaGetSymbolAddress((void**)&qh, g_qh);   cudaGetSymbolAddress((void**)&ql, g_ql);
    cudaGetSymbolAddress((void**)&kh, g_kh);   cudaGetSymbolAddress((void**)&kl, g_kl);
    cudaGetSymbolAddress((void**)&vh, g_vh);   cudaGetSymbolAddress((void**)&vl, g_vl);
    cudaGetSymbolAddress((void**)&xh, g_xh);   cudaGetSymbolAddress((void**)&xl, g_xl);
    cudaGetSymbolAddress((void**)&woh, g_woh); cudaGetSymbolAddress((void**)&wol, g_wol);

    cudaFuncSetAttribute(gemm_qkv, cudaFuncAttributeMaxDynamicSharedMemorySize, GEMM_SMEM);
    cudaFuncSetAttribute(gemm_mma_f32, cudaFuncAttributeMaxDynamicSharedMemorySize, GEMM_SMEM);

    setup_ptrs<<<1, 1>>>(query, key, value, Wq, Wk, Wv, Wo);

    // fused prep
    const int nK4 = BB * SS * DIMC / 4;
    split_all_k<<<dim3(nK4 / 256, 1, 3), 256>>>();
    tsplit_all_k<<<dim3(32, 32, 4), dim3(32, 8)>>>();

    // fused QKV projections (z selects GEMM; Q pre-scaled)
    gemm_qkv<<<dim3(8, 32, 3), 256, GEMM_SMEM>>>();

    // tensor-core flash attention
    attn_mma<<<dim3(LL / 128, BB * NHEADS), 256>>>(qh, ql, kh, kl, vh, vl, xh, xl);

    // output projection (+bias) -> fp32 out
    gemm_mma_f32<<<dim3(8, 16), 256, GEMM_SMEM>>>(xh, xl, woh, wol, bo, out);
}

// round 6
// speedup vs baseline: 4.9034x; 1.2285x over previous
#include <cuda_runtime.h>
#include <cuda_bf16.h>
#include <cstdint>
#include <math.h>

#define DIMC   1024
#define NHEADS 16
#define HDIM   64
#define BB     2
#define LL     1024
#define SS     2048
#define QSCALE 0.125f

// ------------------------- device scratch (bf16 hi/lo pairs) -----------------
__device__ __nv_bfloat16 g_qih[BB * LL * DIMC], g_qil[BB * LL * DIMC];
__device__ __nv_bfloat16 g_kih[BB * SS * DIMC], g_kil[BB * SS * DIMC];
__device__ __nv_bfloat16 g_vih[BB * SS * DIMC], g_vil[BB * SS * DIMC];
__device__ __nv_bfloat16 g_qh[BB * LL * DIMC], g_ql[BB * LL * DIMC];
__device__ __nv_bfloat16 g_kh[BB * SS * DIMC], g_kl[BB * SS * DIMC];
__device__ __nv_bfloat16 g_vh[BB * SS * DIMC], g_vl[BB * SS * DIMC];
__device__ __nv_bfloat16 g_xh[BB * LL * DIMC], g_xl[BB * LL * DIMC];
__device__ __nv_bfloat16 g_wqh[DIMC * DIMC], g_wql[DIMC * DIMC];
__device__ __nv_bfloat16 g_wkh[DIMC * DIMC], g_wkl[DIMC * DIMC];
__device__ __nv_bfloat16 g_wvh[DIMC * DIMC], g_wvl[DIMC * DIMC];
__device__ __nv_bfloat16 g_woh[DIMC * DIMC], g_wol[DIMC * DIMC];

// device-side pointer tables for fused kernels
__device__ const float*         c_splitSrc[3];
__device__ __nv_bfloat16*       c_splitH[3];
__device__ __nv_bfloat16*       c_splitL[3];
__device__ const float*         c_wSrc[4];
__device__ __nv_bfloat16*       c_wH[4];
__device__ __nv_bfloat16*       c_wL[4];
__device__ const __nv_bfloat16* c_gAh[3];
__device__ const __nv_bfloat16* c_gAl[3];
__device__ const __nv_bfloat16* c_gBh[3];
__device__ const __nv_bfloat16* c_gBl[3];
__device__ __nv_bfloat16*       c_gCh[3];
__device__ __nv_bfloat16*       c_gCl[3];

// ------------------------- PTX helpers ----------------------------------------
__device__ __forceinline__ uint32_t smaddr(const void* p) {
    return (uint32_t)__cvta_generic_to_shared(p);
}
__device__ __forceinline__ void cp_async16(void* smem_dst, const void* gmem_src) {
    asm volatile("cp.async.cg.shared.global [%0], [%1], 16;"
                 :: "r"(smaddr(smem_dst)), "l"(gmem_src));
}
__device__ __forceinline__ void cp_commit() {
    asm volatile("cp.async.commit_group;" ::: "memory");
}
__device__ __forceinline__ void cp_wait_all() {
    asm volatile("cp.async.wait_group 0;" ::: "memory");
}
__device__ __forceinline__ void ldsm4(uint32_t* r, uint32_t a) {
    asm volatile("ldmatrix.sync.aligned.m8n8.x4.shared.b16 {%0,%1,%2,%3}, [%4];"
        : "=r"(r[0]), "=r"(r[1]), "=r"(r[2]), "=r"(r[3]) : "r"(a));
}
__device__ __forceinline__ void ldsm4t(uint32_t* r, uint32_t a) {
    asm volatile("ldmatrix.sync.aligned.m8n8.x4.trans.shared.b16 {%0,%1,%2,%3}, [%4];"
        : "=r"(r[0]), "=r"(r[1]), "=r"(r[2]), "=r"(r[3]) : "r"(a));
}
__device__ __forceinline__ void mma16816(float* d, const uint32_t* a, const uint32_t* b)
{
    asm volatile(
        "mma.sync.aligned.m16n8k16.row.col.f32.bf16.bf16.f32 "
        "{%0,%1,%2,%3}, {%4,%5,%6,%7}, {%8,%9}, {%0,%1,%2,%3};"
        : "+f"(d[0]), "+f"(d[1]), "+f"(d[2]), "+f"(d[3])
        : "r"(a[0]), "r"(a[1]), "r"(a[2]), "r"(a[3]), "r"(b[0]), "r"(b[1]));
}
__device__ __forceinline__ uint32_t pack_bf16x2(float a, float b) {
    __nv_bfloat162 h = __floats2bfloat162_rn(a, b);
    return *reinterpret_cast<uint32_t*>(&h);
}

// ------------------------- fused split kernels --------------------------------
__global__ void split_all_k()
{
    const int z = blockIdx.z;
    const int n4 = (z == 0) ? (BB * LL * DIMC / 4) : (BB * SS * DIMC / 4);
    int i = blockIdx.x * 256 + threadIdx.x;
    if (i >= n4) return;
    const float* X = c_splitSrc[z];
    __nv_bfloat16* H = c_splitH[z];
    __nv_bfloat16* L = c_splitL[z];
    float4 x = reinterpret_cast<const float4*>(X)[i];
    __nv_bfloat16 h0 = __float2bfloat16(x.x);
    __nv_bfloat16 h1 = __float2bfloat16(x.y);
    __nv_bfloat16 h2 = __float2bfloat16(x.z);
    __nv_bfloat16 h3 = __float2bfloat16(x.w);
    __nv_bfloat16 l0 = __float2bfloat16(x.x - __bfloat162float(h0));
    __nv_bfloat16 l1 = __float2bfloat16(x.y - __bfloat162float(h1));
    __nv_bfloat16 l2 = __float2bfloat16(x.z - __bfloat162float(h2));
    __nv_bfloat16 l3 = __float2bfloat16(x.w - __bfloat162float(h3));
    reinterpret_cast<__nv_bfloat162*>(H)[2 * i + 0] = __nv_bfloat162(h0, h1);
    reinterpret_cast<__nv_bfloat162*>(H)[2 * i + 1] = __nv_bfloat162(h2, h3);
    reinterpret_cast<__nv_bfloat162*>(L)[2 * i + 0] = __nv_bfloat162(l0, l1);
    reinterpret_cast<__nv_bfloat162*>(L)[2 * i + 1] = __nv_bfloat162(l2, l3);
}

__global__ void tsplit_all_k()
{
    __shared__ float t[32][33];
    const int z = blockIdx.z;
    const float* W = c_wSrc[z];
    __nv_bfloat16* Th = c_wH[z];
    __nv_bfloat16* Tl = c_wL[z];
    const int bx = blockIdx.x * 32;
    const int by = blockIdx.y * 32;
    for (int i = threadIdx.y; i < 32; i += 8)
        t[i][threadIdx.x] = W[(size_t)(by + i) * DIMC + bx + threadIdx.x];
    __syncthreads();
    for (int i = threadIdx.y; i < 32; i += 8) {
        int n = bx + i, k = by + threadIdx.x;
        float x = t[threadIdx.x][i];
        __nv_bfloat16 h = __float2bfloat16(x);
        Th[(size_t)n * DIMC + k] = h;
        Tl[(size_t)n * DIMC + k] = __float2bfloat16(x - __bfloat162float(h));
    }
}

// ------------------------- HMMA GEMM core (cp.async + ldmatrix) ---------------
#define SROW 72
#define SMAT (128 * SROW)
#define SSTAGE (4 * SMAT)
#define GEMM_SMEM (2 * SSTAGE * 2)

template <int B16OUT>
__device__ __forceinline__ void gemm_body(
    const __nv_bfloat16* __restrict__ Ah, const __nv_bfloat16* __restrict__ Al,
    const __nv_bfloat16* __restrict__ Bh, const __nv_bfloat16* __restrict__ Bl,
    const float* __restrict__ bias, float scale,
    float* __restrict__ C, __nv_bfloat16* __restrict__ Ch, __nv_bfloat16* __restrict__ Cl,
    int bm, int bn)
{
    extern __shared__ __align__(16) __nv_bfloat16 sm[];

    const int tid  = threadIdx.x;
    const int lane = tid & 31;
    const int w    = tid >> 5;
    const int wm   = w >> 2;
    const int wn   = w & 3;

    float acc[4][4][4];
#pragma unroll
    for (int i = 0; i < 4; i++)
#pragma unroll
        for (int j = 0; j < 4; j++)
#pragma unroll
            for (int c = 0; c < 4; c++) acc[i][j][c] = 0.f;

    auto cp_chunk = [&](int s, int kc) {
        __nv_bfloat16* dst = sm + s * SSTAGE;
        const __nv_bfloat16* srcA[2] = {Ah, Al};
        const __nv_bfloat16* srcB[2] = {Bh, Bl};
#pragma unroll
        for (int m = 0; m < 2; m++)
#pragma unroll
            for (int it = 0; it < 4; it++) {
                int idx = tid + it * 256;
                int r = idx >> 3, seg = idx & 7;
                cp_async16(dst + m * SMAT + r * SROW + seg * 8,
                           srcA[m] + (size_t)(bm + r) * DIMC + kc + seg * 8);
            }
#pragma unroll
        for (int m = 0; m < 2; m++)
#pragma unroll
            for (int it = 0; it < 4; it++) {
                int idx = tid + it * 256;
                int r = idx >> 3, seg = idx & 7;
                cp_async16(dst + (2 + m) * SMAT + r * SROW + seg * 8,
                           srcB[m] + (size_t)(bn + r) * DIMC + kc + seg * 8);
            }
    };

    cp_chunk(0, 0);
    cp_commit();

    const int g  = lane >> 3;    // ldmatrix lane group
    const int gr = lane & 7;

    for (int ch = 0; ch < 16; ch++) {
        const int cur = ch & 1;
        cp_wait_all();
        __syncthreads();
        if (ch < 15) {
            cp_chunk(cur ^ 1, (ch + 1) * 64);
            cp_commit();
        }

        const __nv_bfloat16* Ahs = sm + cur * SSTAGE;
        const __nv_bfloat16* Als = Ahs + SMAT;
        const __nv_bfloat16* Bhs = Ahs + 2 * SMAT;
        const __nv_bfloat16* Bls = Ahs + 3 * SMAT;

#pragma unroll
        for (int kk = 0; kk < 4; kk++) {
            const int k0 = kk * 16;
            uint32_t ah[4][4], al[4][4], bh[2][4], bl[2][4];
            // A tiles: x4 = one 16x16 tile (a0,a1,a2,a3)
            const int arow = (g & 1) * 8 + gr;
            const int acol = k0 + (g >> 1) * 8;
#pragma unroll
            for (int i = 0; i < 4; i++) {
                int r = wm * 64 + i * 16 + arow;
                ldsm4(ah[i], smaddr(Ahs + r * SROW + acol));
                ldsm4(al[i], smaddr(Als + r * SROW + acol));
            }
            // B tiles: x4 covers j-pair (b0j0,b1j0,b0j1,b1j1)
            const int brow = (g >> 1) * 8 + gr;
            const int bcol = k0 + (g & 1) * 8;
#pragma unroll
            for (int jp = 0; jp < 2; jp++) {
                int r = wn * 32 + jp * 16 + brow;
                ldsm4(bh[jp], smaddr(Bhs + r * SROW + bcol));
                ldsm4(bl[jp], smaddr(Bls + r * SROW + bcol));
            }
#pragma unroll
            for (int i = 0; i < 4; i++)
#pragma unroll
                for (int j = 0; j < 4; j++) {
                    const uint32_t* ph = &bh[j >> 1][(j & 1) * 2];
                    const uint32_t* pl = &bl[j >> 1][(j & 1) * 2];
                    mma16816(acc[i][j], ah[i], ph);
                    mma16816(acc[i][j], ah[i], pl);
                    mma16816(acc[i][j], al[i], ph);
                }
        }
        __syncthreads();
    }

#pragma unroll
    for (int j = 0; j < 4; j++) {
        const int col = bn + wn * 32 + j * 8 + (lane & 3) * 2;
        float b0 = 0.f, b1 = 0.f;
        if (!B16OUT && bias) { b0 = bias[col]; b1 = bias[col + 1]; }
#pragma unroll
        for (int i = 0; i < 4; i++) {
            const int row = bm + wm * 64 + i * 16 + (lane >> 2);
            if (B16OUT) {
#pragma unroll
                for (int half = 0; half < 2; half++) {
                    float v0 = acc[i][j][half * 2 + 0] * scale;
                    float v1 = acc[i][j][half * 2 + 1] * scale;
                    __nv_bfloat162 hh = __floats2bfloat162_rn(v0, v1);
                    __nv_bfloat162 ll = __floats2bfloat162_rn(
                        v0 - __bfloat162float(hh.x), v1 - __bfloat162float(hh.y));
                    size_t off = (size_t)(row + half * 8) * DIMC + col;
                    *reinterpret_cast<uint32_t*>(Ch + off) = *reinterpret_cast<uint32_t*>(&hh);
                    *reinterpret_cast<uint32_t*>(Cl + off) = *reinterpret_cast<uint32_t*>(&ll);
                }
            } else {
                float2 v;
                v.x = acc[i][j][0] + b0;
                v.y = acc[i][j][1] + b1;
                *reinterpret_cast<float2*>(&C[(size_t)row * DIMC + col]) = v;
                v.x = acc[i][j][2] + b0;
                v.y = acc[i][j][3] + b1;
                *reinterpret_cast<float2*>(&C[(size_t)(row + 8) * DIMC + col]) = v;
            }
        }
    }
}

// fused QKV projection, flattened 1-D grid: 128 Q tiles, 256 K, 256 V
__global__ void __launch_bounds__(256, 1)
gemm_qkv(void)
{
    int t = blockIdx.x;
    int z, tile;
    if (t < 128)      { z = 0; tile = t; }
    else if (t < 384) { z = 1; tile = t - 128; }
    else              { z = 2; tile = t - 384; }
    const float scale = (z == 0) ? QSCALE : 1.f;
    gemm_body<1>(c_gAh[z], c_gAl[z], c_gBh[z], c_gBl[z], nullptr, scale,
                 nullptr, c_gCh[z], c_gCl[z], (tile >> 3) * 128, (tile & 7) * 128);
}

__global__ void __launch_bounds__(256, 1)
gemm_mma_f32(const __nv_bfloat16* __restrict__ Ah, const __nv_bfloat16* __restrict__ Al,
             const __nv_bfloat16* __restrict__ Bh, const __nv_bfloat16* __restrict__ Bl,
             const float* __restrict__ bias, float* __restrict__ C)
{
    gemm_body<0>(Ah, Al, Bh, Bl, bias, 1.f, C, nullptr, nullptr,
                 blockIdx.y * 128, blockIdx.x * 128);
}

// ------------------------- HMMA flash attention (ldmatrix) --------------------
#define ATT_KS 72

__global__ void __launch_bounds__(256, 1)
attn_mma(const __nv_bfloat16* __restrict__ Qh, const __nv_bfloat16* __restrict__ Ql,
         const __nv_bfloat16* __restrict__ Kh, const __nv_bfloat16* __restrict__ Kl,
         const __nv_bfloat16* __restrict__ Vh, const __nv_bfloat16* __restrict__ Vl,
         __nv_bfloat16* __restrict__ Xh, __nv_bfloat16* __restrict__ Xl)
{
    __shared__ __nv_bfloat16 Ksh[64 * ATT_KS], Ksl[64 * ATT_KS];
    __shared__ __nv_bfloat16 Vsh[64 * ATT_KS], Vsl[64 * ATT_KS];

    const int tid = threadIdx.x, lane = tid & 31, w = tid >> 5;
    const int b = blockIdx.y >> 4, h = blockIdx.y & 15;
    const int r0 = blockIdx.x * 128;
    const int qr = lane >> 2;
    const int qc = (lane & 3) * 2;
    const int g  = lane >> 3;
    const int gr = lane & 7;

    uint32_t qfh[4][4], qfl[4][4];
#pragma unroll
    for (int kk = 0; kk < 4; kk++) {
#pragma unroll
        for (int r = 0; r < 4; r++) {
            int row = r0 + w * 16 + qr + (r & 1) * 8;
            int col = h * HDIM + kk * 16 + qc + (r >> 1) * 8;
            size_t off = (size_t)(b * LL + row) * DIMC + col;
            qfh[kk][r] = *reinterpret_cast<const uint32_t*>(Qh + off);
            qfl[kk][r] = *reinterpret_cast<const uint32_t*>(Ql + off);
        }
    }

    float m0 = -INFINITY, m1 = -INFINITY, l0 = 0.f, l1 = 0.f;
    float o[8][4];
#pragma unroll
    for (int j = 0; j < 8; j++)
#pragma unroll
        for (int c = 0; c < 4; c++) o[j][c] = 0.f;

    for (int s0 = 0; s0 < SS; s0 += 64) {
        __syncthreads();
        // stage K and V, both key-major (coalesced int4)
#pragma unroll
        for (int i = 0; i < 2; i++) {
            int idx = tid + i * 256;
            int key = idx >> 3, seg = idx & 7;
            size_t gaddr = (size_t)(b * SS + s0 + key) * DIMC + h * HDIM + seg * 8;
            *reinterpret_cast<int4*>(Ksh + key * ATT_KS + seg * 8) =
                *reinterpret_cast<const int4*>(Kh + gaddr);
            *reinterpret_cast<int4*>(Ksl + key * ATT_KS + seg * 8) =
                *reinterpret_cast<const int4*>(Kl + gaddr);
            *reinterpret_cast<int4*>(Vsh + key * ATT_KS + seg * 8) =
                *reinterpret_cast<const int4*>(Vh + gaddr);
            *reinterpret_cast<int4*>(Vsl + key * ATT_KS + seg * 8) =
                *reinterpret_cast<const int4*>(Vl + gaddr);
        }
        __syncthreads();

        // ---- scores S = Q K^T (3-product split), B frags via ldmatrix.x4 ----
        float sc[8][4];
#pragma unroll
        for (int j = 0; j < 8; j++)
#pragma unroll
            for (int c = 0; c < 4; c++) sc[j][c] = 0.f;

#pragma unroll
        for (int kk = 0; kk < 4; kk++) {
            const int bcol = kk * 16 + (g & 1) * 8;
            const int brow = (g >> 1) * 8 + gr;
#pragma unroll
            for (int jnp = 0; jnp < 4; jnp++) {
                int r = jnp * 16 + brow;
                uint32_t bh[4], bl[4];
                ldsm4(bh, smaddr(Ksh + r * ATT_KS + bcol));
                ldsm4(bl, smaddr(Ksl + r * ATT_KS + bcol));
                mma16816(sc[2 * jnp],     qfh[kk], bh);
                mma16816(sc[2 * jnp],     qfh[kk], bl);
                mma16816(sc[2 * jnp],     qfl[kk], bh);
                mma16816(sc[2 * jnp + 1], qfh[kk], bh + 2);
                mma16816(sc[2 * jnp + 1], qfh[kk], bl + 2);
                mma16816(sc[2 * jnp + 1], qfl[kk], bh + 2);
            }
        }

        // ---- online softmax (rows qr, qr+8) ----
        float r0max = -INFINITY, r1max = -INFINITY;
#pragma unroll
        for (int j = 0; j < 8; j++) {
            r0max = fmaxf(r0max, fmaxf(sc[j][0], sc[j][1]));
            r1max = fmaxf(r1max, fmaxf(sc[j][2], sc[j][3]));
        }
        r0max = fmaxf(r0max, __shfl_xor_sync(0xffffffffu, r0max, 1));
        r0max = fmaxf(r0max, __shfl_xor_sync(0xffffffffu, r0max, 2));
        r1max = fmaxf(r1max, __shfl_xor_sync(0xffffffffu, r1max, 1));
        r1max = fmaxf(r1max, __shfl_xor_sync(0xffffffffu, r1max, 2));
        float mn0 = fmaxf(m0, r0max), mn1 = fmaxf(m1, r1max);
        float c0 = __expf(m0 - mn0), c1 = __expf(m1 - mn1);
        m0 = mn0; m1 = mn1;

        float ps0 = 0.f, ps1 = 0.f;
#pragma unroll
        for (int j = 0; j < 8; j++) {
            sc[j][0] = __expf(sc[j][0] - mn0);
            sc[j][1] = __expf(sc[j][1] - mn0);
            sc[j][2] = __expf(sc[j][2] - mn1);
            sc[j][3] = __expf(sc[j][3] - mn1);
            ps0 += sc[j][0] + sc[j][1];
            ps1 += sc[j][2] + sc[j][3];
        }
        ps0 += __shfl_xor_sync(0xffffffffu, ps0, 1);
        ps0 += __shfl_xor_sync(0xffffffffu, ps0, 2);
        ps1 += __shfl_xor_sync(0xffffffffu, ps1, 1);
        ps1 += __shfl_xor_sync(0xffffffffu, ps1, 2);
        l0 = l0 * c0 + ps0;
        l1 = l1 * c1 + ps1;
#pragma unroll
        for (int j = 0; j < 8; j++) {
            o[j][0] *= c0; o[j][1] *= c0;
            o[j][2] *= c1; o[j][3] *= c1;
        }

        // ---- O += P V (3-product), V frags via ldmatrix.x4.trans ----
#pragma unroll
        for (int kk = 0; kk < 4; kk++) {
            uint32_t pah[4], pal[4];
            {
                float p00 = sc[2 * kk][0],     p01 = sc[2 * kk][1];
                float p10 = sc[2 * kk][2],     p11 = sc[2 * kk][3];
                float p20 = sc[2 * kk + 1][0], p21 = sc[2 * kk + 1][1];
                float p30 = sc[2 * kk + 1][2], p31 = sc[2 * kk + 1][3];
                __nv_bfloat162 t;
                t = __floats2bfloat162_rn(p00, p01); pah[0] = *reinterpret_cast<uint32_t*>(&t);
                pal[0] = pack_bf16x2(p00 - __bfloat162float(t.x), p01 - __bfloat162float(t.y));
                t = __floats2bfloat162_rn(p10, p11); pah[1] = *reinterpret_cast<uint32_t*>(&t);
                pal[1] = pack_bf16x2(p10 - __bfloat162float(t.x), p11 - __bfloat162float(t.y));
                t = __floats2bfloat162_rn(p20, p21); pah[2] = *reinterpret_cast<uint32_t*>(&t);
                pal[2] = pack_bf16x2(p20 - __bfloat162float(t.x), p21 - __bfloat162float(t.y));
                t = __floats2bfloat162_rn(p30, p31); pah[3] = *reinterpret_cast<uint32_t*>(&t);
                pal[3] = pack_bf16x2(p30 - __bfloat162float(t.x), p31 - __bfloat162float(t.y));
            }
            // V fragment: keys kk*16..+15 x dims (2 dim-tiles per LDSM)
            const int vkey = kk * 16 + (g & 1) * 8 + gr;
#pragma unroll
            for (int jdp = 0; jdp < 4; jdp++) {
                const int vcol = (jdp * 2 + (g >> 1)) * 8;
                uint32_t vh[4], vl[4];
                ldsm4t(vh, smaddr(Vsh + vkey * ATT_KS + vcol));
                ldsm4t(vl, smaddr(Vsl + vkey * ATT_KS + vcol));
                mma16816(o[2 * jdp],     pah, vh);
                mma16816(o[2 * jdp],     pah, vl);
                mma16816(o[2 * jdp],     pal, vh);
                mma16816(o[2 * jdp + 1], pah, vh + 2);
                mma16816(o[2 * jdp + 1], pah, vl + 2);
                mma16816(o[2 * jdp + 1], pal, vh + 2);
            }
        }
    }

    float i0 = 1.f / l0, i1 = 1.f / l1;
#pragma unroll
    for (int jd = 0; jd < 8; jd++) {
        int col = h * HDIM + jd * 8 + qc;
        int row0 = r0 + w * 16 + qr;
        float v0 = o[jd][0] * i0, v1 = o[jd][1] * i0;
        __nv_bfloat162 hh = __floats2bfloat162_rn(v0, v1);
        __nv_bfloat162 ll = __floats2bfloat162_rn(
            v0 - __bfloat162float(hh.x), v1 - __bfloat162float(hh.y));
        size_t off = (size_t)(b * LL + row0) * DIMC + col;
        *reinterpret_cast<uint32_t*>(Xh + off) = *reinterpret_cast<uint32_t*>(&hh);
        *reinterpret_cast<uint32_t*>(Xl + off) = *reinterpret_cast<uint32_t*>(&ll);

        float v2 = o[jd][2] * i1, v3 = o[jd][3] * i1;
        hh = __floats2bfloat162_rn(v2, v3);
        ll = __floats2bfloat162_rn(v2 - __bfloat162float(hh.x), v3 - __bfloat162float(hh.y));
        off = (size_t)(b * LL + row0 + 8) * DIMC + col;
        *reinterpret_cast<uint32_t*>(Xh + off) = *reinterpret_cast<uint32_t*>(&hh);
        *reinterpret_cast<uint32_t*>(Xl + off) = *reinterpret_cast<uint32_t*>(&ll);
    }
}

// setup kernel: fill device pointer tables
__global__ void setup_ptrs(const float* query, const float* key, const float* value,
                           const float* Wq, const float* Wk, const float* Wv, const float* Wo)
{
    c_splitSrc[0] = query; c_splitSrc[1] = key; c_splitSrc[2] = value;
    c_splitH[0] = g_qih; c_splitL[0] = g_qil;
    c_splitH[1] = g_kih; c_splitL[1] = g_kil;
    c_splitH[2] = g_vih; c_splitL[2] = g_vil;
    c_wSrc[0] = Wq; c_wSrc[1] = Wk; c_wSrc[2] = Wv; c_wSrc[3] = Wo;
    c_wH[0] = g_wqh; c_wL[0] = g_wql;
    c_wH[1] = g_wkh; c_wL[1] = g_wkl;
    c_wH[2] = g_wvh; c_wL[2] = g_wvl;
    c_wH[3] = g_woh; c_wL[3] = g_wol;
    c_gAh[0] = g_qih; c_gAl[0] = g_qil; c_gBh[0] = g_wqh; c_gBl[0] = g_wql;
    c_gCh[0] = g_qh;  c_gCl[0] = g_ql;
    c_gAh[1] = g_kih; c_gAl[1] = g_kil; c_gBh[1] = g_wkh; c_gBl[1] = g_wkl;
    c_gCh[1] = g_kh;  c_gCl[1] = g_kl;
    c_gAh[2] = g_vih; c_gAl[2] = g_vil; c_gBh[2] = g_wvh; c_gBl[2] = g_wvl;
    c_gCh[2] = g_vh;  c_gCl[2] = g_vl;
}

// ------------------------------- launch --------------------------------------
extern "C" void kernel_launch(void* const* d_in, const int* in_sizes, int n_in,
                              void* d_out, int out_size)
{
    const float* query = (const float*)d_in[0];
    const float* key   = (const float*)d_in[1];
    const float* value = (const float*)d_in[2];
    const float* Wq    = (const float*)d_in[3];
    const float* Wk    = (const float*)d_in[4];
    const float* Wv    = (const float*)d_in[5];
    const float* Wo    = (const float*)d_in[6];
    const float* bo    = (const float*)d_in[7];
    float* out = (float*)d_out;

    __nv_bfloat16 *qh, *ql, *kh, *kl, *vh, *vl, *xh, *xl, *woh, *wol;
    cudaGetSymbolAddress((void**)&qh, g_qh);   cudaGetSymbolAddress((void**)&ql, g_ql);
    cudaGetSymbolAddress((void**)&kh, g_kh);   cudaGetSymbolAddress((void**)&kl, g_kl);
    cudaGetSymbolAddress((void**)&vh, g_vh);   cudaGetSymbolAddress((void**)&vl, g_vl);
    cudaGetSymbolAddress((void**)&xh, g_xh);   cudaGetSymbolAddress((void**)&xl, g_xl);
    cudaGetSymbolAddress((void**)&woh, g_woh); cudaGetSymbolAddress((void**)&wol, g_wol);

    cudaFuncSetAttribute(gemm_qkv, cudaFuncAttributeMaxDynamicSharedMemorySize, GEMM_SMEM);
    cudaFuncSetAttribute(gemm_mma_f32, cudaFuncAttributeMaxDynamicSharedMemorySize, GEMM_SMEM);

    setup_ptrs<<<1, 1>>>(query, key, value, Wq, Wk, Wv, Wo);

    const int nK4 = BB * SS * DIMC / 4;
    split_all_k<<<dim3(nK4 / 256, 1, 3), 256>>>();
    tsplit_all_k<<<dim3(32, 32, 4), dim3(32, 8)>>>();

    gemm_qkv<<<640, 256, GEMM_SMEM>>>();

    attn_mma<<<dim3(LL / 128, BB * NHEADS), 256>>>(qh, ql, kh, kl, vh, vl, xh, xl);

    gemm_mma_f32<<<dim3(8, 16), 256, GEMM_SMEM>>>(xh, xl, woh, wol, bo, out);
}